// round 1
// baseline (speedup 1.0000x reference)
#include <cuda_runtime.h>
#include <math.h>

#define NB     16
#define NPTS   50000
#define HD     128
#define NL     5
#define NO     5
#define PDIM   8
#define TILE_N 64
#define LDX    132   // padded row stride for activation tile (avoids bank conflicts)

// Scratch for branch outputs (allocation-free per harness rules)
__device__ float g_S [NB * NL * HD];   // FiLM cumsums S_i, layout [b][i][h]
__device__ float g_ZL[NB * NO * HD];   // branch_out reshaped, layout [b][o][h]

// ---------------------------------------------------------------------------
// Branch MLP: B=16 rows, tiny. One block per batch, one thread per hidden unit.
// ---------------------------------------------------------------------------
__global__ void branch_kernel(const float* __restrict__ params,
                              const float* __restrict__ W0,
                              const float* __restrict__ b0,
                              const float* __restrict__ Wh,
                              const float* __restrict__ bh,
                              const float* __restrict__ alpha,
                              const float* __restrict__ Wf,
                              const float* __restrict__ bf)
{
    const int b = blockIdx.x;
    const int j = threadIdx.x;
    __shared__ float hs[HD];
    __shared__ float ps[PDIM];
    if (j < PDIM) ps[j] = params[b * PDIM + j];
    __syncthreads();

    float acc = b0[j];
#pragma unroll
    for (int k = 0; k < PDIM; ++k) acc = fmaf(ps[k], W0[k * HD + j], acc);
    float hv = alpha[j] * tanhf(acc);
    float S = hv;
    g_S[(b * NL + 0) * HD + j] = S;

    for (int i = 0; i < NL - 1; ++i) {
        hs[j] = hv;
        __syncthreads();
        float a2 = bh[i * HD + j];
#pragma unroll 8
        for (int k = 0; k < HD; ++k)
            a2 = fmaf(hs[k], Wh[(i * HD + k) * HD + j], a2);
        hv = alpha[(i + 1) * HD + j] * tanhf(a2);
        S += hv;
        g_S[(b * NL + i + 1) * HD + j] = S;
        __syncthreads();
    }

    hs[j] = hv;
    __syncthreads();
#pragma unroll
    for (int o = 0; o < NO; ++o) {
        float a2 = bf[o * HD + j];
#pragma unroll 8
        for (int k = 0; k < HD; ++k)
            a2 = fmaf(hs[k], Wf[k * (HD * NO) + o * HD + j], a2);
        g_ZL[(b * NO + o) * HD + j] = a2;
    }
}

// ---------------------------------------------------------------------------
// Trunk: fully fused. One CTA = (64-point tile, one batch).
// smem: activation tile xs[64][132], weights Ws[128][128], per-layer vectors,
//       ZL (5x128), coords tile. Thread micro-tile: 4 points x 8 cols.
// ---------------------------------------------------------------------------

__device__ __forceinline__ void matmul_tile(const float* __restrict__ xs,
                                            const float* __restrict__ Ws,
                                            int row, int col, float acc[4][8])
{
#pragma unroll 4
    for (int k = 0; k < HD; ++k) {
        float a0 = xs[(row + 0) * LDX + k];
        float a1 = xs[(row + 1) * LDX + k];
        float a2 = xs[(row + 2) * LDX + k];
        float a3 = xs[(row + 3) * LDX + k];
        float4 w0 = *(const float4*)&Ws[k * HD + col];
        float4 w1 = *(const float4*)&Ws[k * HD + col + 4];
        float w[8] = {w0.x, w0.y, w0.z, w0.w, w1.x, w1.y, w1.z, w1.w};
        float a[4] = {a0, a1, a2, a3};
#pragma unroll
        for (int i = 0; i < 4; ++i)
#pragma unroll
            for (int jj = 0; jj < 8; ++jj)
                acc[i][jj] = fmaf(a[i], w[jj], acc[i][jj]);
    }
}

__device__ __forceinline__ void store_tile(float* __restrict__ xs,
                                           int row, int col, const float acc[4][8])
{
#pragma unroll
    for (int i = 0; i < 4; ++i) {
        *(float4*)&xs[(row + i) * LDX + col] =
            make_float4(acc[i][0], acc[i][1], acc[i][2], acc[i][3]);
        *(float4*)&xs[(row + i) * LDX + col + 4] =
            make_float4(acc[i][4], acc[i][5], acc[i][6], acc[i][7]);
    }
}

__device__ __forceinline__ void load_layer(float* __restrict__ Ws,
                                           float* __restrict__ sB,
                                           float* __restrict__ sS,
                                           float* __restrict__ sA,
                                           const float* __restrict__ W,
                                           const float* __restrict__ bias,
                                           const float* __restrict__ Svec,
                                           const float* __restrict__ avec,
                                           int tid)
{
    const float4* src = (const float4*)W;
    float4* dst = (float4*)Ws;
#pragma unroll
    for (int idx = tid; idx < HD * HD / 4; idx += 256) dst[idx] = src[idx];
    if (tid < HD) {
        sB[tid] = bias[tid];
        if (Svec) sS[tid] = Svec[tid];
        if (avec) sA[tid] = avec[tid];
    }
}

__global__ __launch_bounds__(256, 2)
void trunk_kernel(const float* __restrict__ coords,
                  const float* __restrict__ W0,
                  const float* __restrict__ b0,
                  const float* __restrict__ Wh,
                  const float* __restrict__ bh,
                  const float* __restrict__ alpha,
                  const float* __restrict__ Wf,
                  const float* __restrict__ bf,
                  float* __restrict__ out)
{
    extern __shared__ float sm[];
    float* xs = sm;                       // TILE_N * LDX
    float* Ws = xs + TILE_N * LDX;        // HD * HD
    float* sS = Ws + HD * HD;             // HD
    float* sB = sS + HD;                  // HD
    float* sA = sB + HD;                  // HD
    float* sZ = sA + HD;                  // NO * HD
    float* sC = sZ + NO * HD;             // TILE_N * 3

    const int b   = blockIdx.y;
    const int n0  = blockIdx.x * TILE_N;
    const int nv  = min(TILE_N, NPTS - n0);
    const int tid = threadIdx.x;
    const int tx  = tid & 15;
    const int ty  = tid >> 4;
    const int col = tx * 8;
    const int row = ty * 4;

    // ---- prologue loads: ZL, layer-0 weights, biases/FiLM/alpha, coords ----
    for (int idx = tid; idx < NO * HD; idx += 256) sZ[idx] = g_ZL[b * NO * HD + idx];
    for (int idx = tid; idx < 3 * HD; idx += 256)  Ws[idx] = W0[idx];
    if (tid < HD) {
        sB[tid] = b0[tid];
        sA[tid] = alpha[tid];
        sS[tid] = g_S[(b * NL + 0) * HD + tid];
    }
    for (int idx = tid; idx < TILE_N * 3; idx += 256)
        sC[idx] = (idx < nv * 3) ? coords[(b * NPTS + n0) * 3 + idx] : 0.f;
    __syncthreads();

    float acc[4][8];

    // ---- layer 0: coords (3) -> H, then FiLM-tanh ----
    {
        float bia[8], alph[8], sfac[8];
#pragma unroll
        for (int jj = 0; jj < 8; ++jj) {
            bia[jj]  = sB[col + jj];
            alph[jj] = sA[col + jj];
            sfac[jj] = sS[col + jj];
        }
#pragma unroll
        for (int i = 0; i < 4; ++i) {
            float c0 = sC[(row + i) * 3 + 0];
            float c1 = sC[(row + i) * 3 + 1];
            float c2 = sC[(row + i) * 3 + 2];
#pragma unroll
            for (int jj = 0; jj < 8; ++jj) {
                float v = bia[jj];
                v = fmaf(c0, Ws[0 * HD + col + jj], v);
                v = fmaf(c1, Ws[1 * HD + col + jj], v);
                v = fmaf(c2, Ws[2 * HD + col + jj], v);
                acc[i][jj] = alph[jj] * tanhf(v * sfac[jj]);
            }
        }
        __syncthreads();                       // done reading Ws/sB/sS/sA/sC
        store_tile(xs, row, col, acc);
        load_layer(Ws, sB, sS, sA,
                   Wh + 0 * HD * HD, bh + 0 * HD,
                   &g_S[(b * NL + 1) * HD], alpha + 1 * HD, tid);
        __syncthreads();
    }

    // ---- hidden layers t = 1..4 ----
#pragma unroll 1
    for (int t = 1; t <= 4; ++t) {
        float bia[8], alph[8], sfac[8];
#pragma unroll
        for (int jj = 0; jj < 8; ++jj) {
            bia[jj]  = sB[col + jj];
            alph[jj] = sA[col + jj];
            sfac[jj] = sS[col + jj];
        }
#pragma unroll
        for (int i = 0; i < 4; ++i)
#pragma unroll
            for (int jj = 0; jj < 8; ++jj) acc[i][jj] = bia[jj];

        matmul_tile(xs, Ws, row, col, acc);

#pragma unroll
        for (int i = 0; i < 4; ++i)
#pragma unroll
            for (int jj = 0; jj < 8; ++jj)
                acc[i][jj] = alph[jj] * tanhf(acc[i][jj] * sfac[jj]);

        __syncthreads();                       // done reading xs/Ws/vectors
        store_tile(xs, row, col, acc);
        if (t < 4) {
            load_layer(Ws, sB, sS, sA,
                       Wh + t * HD * HD, bh + t * HD,
                       &g_S[(b * NL + t + 1) * HD], alpha + (t + 1) * HD, tid);
        } else {
            load_layer(Ws, sB, sS, sA, Wf, bf, nullptr, nullptr, tid);
        }
        __syncthreads();
    }

    // ---- final trunk layer: YL = x @ Wf + bf (no activation) ----
    {
        float bia[8];
#pragma unroll
        for (int jj = 0; jj < 8; ++jj) bia[jj] = sB[col + jj];
#pragma unroll
        for (int i = 0; i < 4; ++i)
#pragma unroll
            for (int jj = 0; jj < 8; ++jj) acc[i][jj] = bia[jj];

        matmul_tile(xs, Ws, row, col, acc);

        __syncthreads();
        store_tile(xs, row, col, acc);         // xs now holds YL
        __syncthreads();
    }

    // ---- output einsum: out[b,n,o] = sum_h ZL[b,o,h] * YL[n,h] ----
    for (int idx = tid; idx < nv * NO; idx += 256) {
        int p = idx / NO;
        int o = idx - p * NO;
        const float* zp = sZ + o * HD;
        const float* yp = xs + p * LDX;
        float s = 0.f;
#pragma unroll 16
        for (int h = 0; h < HD; ++h) s = fmaf(zp[h], yp[h], s);
        out[((long)b * NPTS + n0 + p) * NO + o] = s;
    }
}

// ---------------------------------------------------------------------------
// Launch
// ---------------------------------------------------------------------------
extern "C" void kernel_launch(void* const* d_in, const int* in_sizes, int n_in,
                              void* d_out, int out_size)
{
    const float* coords = (const float*)d_in[0];
    const float* params = (const float*)d_in[1];
    const float* bW0    = (const float*)d_in[2];
    const float* bb0    = (const float*)d_in[3];
    const float* bWh    = (const float*)d_in[4];
    const float* bbh    = (const float*)d_in[5];
    const float* balpha = (const float*)d_in[6];
    const float* bWf    = (const float*)d_in[7];
    const float* bbf    = (const float*)d_in[8];
    const float* tW0    = (const float*)d_in[9];
    const float* tb0    = (const float*)d_in[10];
    const float* tWh    = (const float*)d_in[11];
    const float* tbh    = (const float*)d_in[12];
    const float* talpha = (const float*)d_in[13];
    const float* tWf    = (const float*)d_in[14];
    const float* tbf    = (const float*)d_in[15];
    float* out = (float*)d_out;

    constexpr int SMEM_FLOATS =
        TILE_N * LDX + HD * HD + 3 * HD + NO * HD + TILE_N * 3;
    constexpr size_t SMEM_BYTES = SMEM_FLOATS * sizeof(float);

    cudaFuncSetAttribute(trunk_kernel,
                         cudaFuncAttributeMaxDynamicSharedMemorySize,
                         (int)SMEM_BYTES);

    branch_kernel<<<NB, HD>>>(params, bW0, bb0, bWh, bbh, balpha, bWf, bbf);

    dim3 grid((NPTS + TILE_N - 1) / TILE_N, NB);
    trunk_kernel<<<grid, 256, SMEM_BYTES>>>(coords, tW0, tb0, tWh, tbh,
                                            talpha, tWf, tbf, out);
}

// round 2
// speedup vs baseline: 1.4802x; 1.4802x over previous
#include <cuda_runtime.h>
#include <math.h>

#define NB     16
#define NPTS   50000
#define HD     128
#define NL     5
#define NO     5
#define PDIM   8
#define TILE_N 64
#define LDX    136   // padded row stride, multiple of 4 for float4 alignment

// Scratch for branch outputs (allocation-free per harness rules)
__device__ float g_S [NB * NL * HD];   // FiLM cumsums S_i, layout [b][i][h]
__device__ float g_ZL[NB * NO * HD];   // branch_out reshaped, layout [b][o][h]

// ---------------- packed f32x2 helpers ----------------
__device__ __forceinline__ unsigned long long pack2(float lo, float hi) {
    unsigned long long r;
    asm("mov.b64 %0, {%1, %2};" : "=l"(r)
        : "r"(__float_as_uint(lo)), "r"(__float_as_uint(hi)));
    return r;
}
__device__ __forceinline__ unsigned long long dup2(float v) {
    unsigned long long r;
    unsigned int b = __float_as_uint(v);
    asm("mov.b64 %0, {%1, %1};" : "=l"(r) : "r"(b));
    return r;
}
__device__ __forceinline__ void unpack2(unsigned long long v, float& lo, float& hi) {
    unsigned int a, b;
    asm("mov.b64 {%0, %1}, %2;" : "=r"(a), "=r"(b) : "l"(v));
    lo = __uint_as_float(a);
    hi = __uint_as_float(b);
}
#define FFMA2(acc, a, w) \
    asm("fma.rn.f32x2 %0, %1, %2, %0;" : "+l"(acc) : "l"(a), "l"(w))

__device__ __forceinline__ float tanh_fast(float x) {
    float t;
    asm("tanh.approx.f32 %0, %1;" : "=f"(t) : "f"(x));
    return t;
}

// ---------------------------------------------------------------------------
// Branch MLP: B=16 rows, tiny. Exact tanhf (feeds everything downstream).
// ---------------------------------------------------------------------------
__global__ void branch_kernel(const float* __restrict__ params,
                              const float* __restrict__ W0,
                              const float* __restrict__ b0,
                              const float* __restrict__ Wh,
                              const float* __restrict__ bh,
                              const float* __restrict__ alpha,
                              const float* __restrict__ Wf,
                              const float* __restrict__ bf)
{
    const int b = blockIdx.x;
    const int j = threadIdx.x;
    __shared__ float hs[HD];
    __shared__ float ps[PDIM];
    if (j < PDIM) ps[j] = params[b * PDIM + j];
    __syncthreads();

    float acc = b0[j];
#pragma unroll
    for (int k = 0; k < PDIM; ++k) acc = fmaf(ps[k], W0[k * HD + j], acc);
    float hv = alpha[j] * tanhf(acc);
    float S = hv;
    g_S[(b * NL + 0) * HD + j] = S;

    for (int i = 0; i < NL - 1; ++i) {
        hs[j] = hv;
        __syncthreads();
        float a2 = bh[i * HD + j];
#pragma unroll 8
        for (int k = 0; k < HD; ++k)
            a2 = fmaf(hs[k], Wh[(i * HD + k) * HD + j], a2);
        hv = alpha[(i + 1) * HD + j] * tanhf(a2);
        S += hv;
        g_S[(b * NL + i + 1) * HD + j] = S;
        __syncthreads();
    }

    hs[j] = hv;
    __syncthreads();
#pragma unroll
    for (int o = 0; o < NO; ++o) {
        float a2 = bf[o * HD + j];
#pragma unroll 8
        for (int k = 0; k < HD; ++k)
            a2 = fmaf(hs[k], Wf[k * (HD * NO) + o * HD + j], a2);
        g_ZL[(b * NO + o) * HD + j] = a2;
    }
}

// ---------------------------------------------------------------------------
// Trunk: fully fused. One CTA = (64-point tile, one batch), 128 threads.
// Thread micro-tile: 8 points x 8 cols, accumulated as 8x4 packed f32x2.
// ---------------------------------------------------------------------------

// acc2[i][j] holds cols (col+2j, col+2j+1) for row (row+i), packed lo/hi.
__device__ __forceinline__ void matmul_tile2(const float* __restrict__ xs,
                                             const float* __restrict__ Ws,
                                             int row, int col,
                                             unsigned long long acc2[8][4])
{
#pragma unroll 2
    for (int k = 0; k < HD; k += 4) {
        float4 a4[8];
#pragma unroll
        for (int i = 0; i < 8; ++i)
            a4[i] = *(const float4*)&xs[(row + i) * LDX + k];
#pragma unroll
        for (int kk = 0; kk < 4; ++kk) {
            ulonglong2 wlo = *(const ulonglong2*)&Ws[(k + kk) * HD + col];
            ulonglong2 whi = *(const ulonglong2*)&Ws[(k + kk) * HD + col + 4];
#pragma unroll
            for (int i = 0; i < 8; ++i) {
                float av = (kk == 0) ? a4[i].x : (kk == 1) ? a4[i].y
                         : (kk == 2) ? a4[i].z : a4[i].w;
                unsigned long long ad = dup2(av);
                FFMA2(acc2[i][0], ad, wlo.x);
                FFMA2(acc2[i][1], ad, wlo.y);
                FFMA2(acc2[i][2], ad, whi.x);
                FFMA2(acc2[i][3], ad, whi.y);
            }
        }
    }
}

__device__ __forceinline__ void store_tile2(float* __restrict__ xs,
                                            int row, int col,
                                            const unsigned long long acc2[8][4])
{
#pragma unroll
    for (int i = 0; i < 8; ++i) {
        *(ulonglong2*)&xs[(row + i) * LDX + col]     =
            make_ulonglong2(acc2[i][0], acc2[i][1]);
        *(ulonglong2*)&xs[(row + i) * LDX + col + 4] =
            make_ulonglong2(acc2[i][2], acc2[i][3]);
    }
}

__device__ __forceinline__ void load_layer(float* __restrict__ Ws,
                                           float* __restrict__ sB,
                                           float* __restrict__ sS,
                                           float* __restrict__ sA,
                                           const float* __restrict__ W,
                                           const float* __restrict__ bias,
                                           const float* __restrict__ Svec,
                                           const float* __restrict__ avec,
                                           int tid)
{
    const float4* src = (const float4*)W;
    float4* dst = (float4*)Ws;
#pragma unroll
    for (int idx = tid; idx < HD * HD / 4; idx += 128) dst[idx] = src[idx];
    if (tid < HD) {
        sB[tid] = bias[tid];
        if (Svec) sS[tid] = Svec[tid];
        if (avec) sA[tid] = avec[tid];
    }
}

__global__ __launch_bounds__(128, 2)
void trunk_kernel(const float* __restrict__ coords,
                  const float* __restrict__ W0,
                  const float* __restrict__ b0,
                  const float* __restrict__ Wh,
                  const float* __restrict__ bh,
                  const float* __restrict__ alpha,
                  const float* __restrict__ Wf,
                  const float* __restrict__ bf,
                  float* __restrict__ out)
{
    extern __shared__ float sm[];
    float* xs = sm;                       // TILE_N * LDX
    float* Ws = xs + TILE_N * LDX;        // HD * HD
    float* sS = Ws + HD * HD;             // HD
    float* sB = sS + HD;                  // HD
    float* sA = sB + HD;                  // HD
    float* sZ = sA + HD;                  // NO * HD
    float* sC = sZ + NO * HD;             // TILE_N * 3

    const int b   = blockIdx.y;
    const int n0  = blockIdx.x * TILE_N;
    const int nv  = min(TILE_N, NPTS - n0);
    const int tid = threadIdx.x;
    const int tx  = tid & 15;             // 16 col groups
    const int ty  = tid >> 4;             // 8 row groups
    const int col = tx * 8;
    const int row = ty * 8;

    // ---- prologue loads ----
    for (int idx = tid; idx < NO * HD; idx += 128) sZ[idx] = g_ZL[b * NO * HD + idx];
    for (int idx = tid; idx < 3 * HD; idx += 128)  Ws[idx] = W0[idx];
    if (tid < HD) {
        sB[tid] = b0[tid];
        sA[tid] = alpha[tid];
        sS[tid] = g_S[(b * NL + 0) * HD + tid];
    }
    for (int idx = tid; idx < TILE_N * 3; idx += 128)
        sC[idx] = (idx < nv * 3) ? coords[(b * NPTS + n0) * 3 + idx] : 0.f;
    __syncthreads();

    unsigned long long acc2[8][4];

    // ---- layer 0: coords (3) -> H, then FiLM-tanh ----
    {
        float bia[8], alph[8], sfac[8], w0c[8], w1c[8], w2c[8];
#pragma unroll
        for (int jj = 0; jj < 8; ++jj) {
            bia[jj]  = sB[col + jj];
            alph[jj] = sA[col + jj];
            sfac[jj] = sS[col + jj];
            w0c[jj]  = Ws[0 * HD + col + jj];
            w1c[jj]  = Ws[1 * HD + col + jj];
            w2c[jj]  = Ws[2 * HD + col + jj];
        }
#pragma unroll
        for (int i = 0; i < 8; ++i) {
            float c0 = sC[(row + i) * 3 + 0];
            float c1 = sC[(row + i) * 3 + 1];
            float c2 = sC[(row + i) * 3 + 2];
            float v[8];
#pragma unroll
            for (int jj = 0; jj < 8; ++jj) {
                float t = bia[jj];
                t = fmaf(c0, w0c[jj], t);
                t = fmaf(c1, w1c[jj], t);
                t = fmaf(c2, w2c[jj], t);
                v[jj] = alph[jj] * tanh_fast(t * sfac[jj]);
            }
#pragma unroll
            for (int jj = 0; jj < 4; ++jj)
                acc2[i][jj] = pack2(v[2 * jj], v[2 * jj + 1]);
        }
        __syncthreads();                       // done reading Ws/sB/sS/sA/sC
        store_tile2(xs, row, col, acc2);
        load_layer(Ws, sB, sS, sA,
                   Wh + 0 * HD * HD, bh + 0 * HD,
                   &g_S[(b * NL + 1) * HD], alpha + 1 * HD, tid);
        __syncthreads();
    }

    // ---- hidden layers t = 1..4 ----
#pragma unroll 1
    for (int t = 1; t <= 4; ++t) {
        float sfac[8], alph[8];
#pragma unroll
        for (int jj = 0; jj < 8; ++jj) {
            sfac[jj] = sS[col + jj];
            alph[jj] = sA[col + jj];
        }
#pragma unroll
        for (int jj = 0; jj < 4; ++jj) {
            unsigned long long bp = pack2(sB[col + 2 * jj], sB[col + 2 * jj + 1]);
#pragma unroll
            for (int i = 0; i < 8; ++i) acc2[i][jj] = bp;
        }

        matmul_tile2(xs, Ws, row, col, acc2);

        // FiLM + rowdy tanh (approx), repack
#pragma unroll
        for (int i = 0; i < 8; ++i)
#pragma unroll
            for (int jj = 0; jj < 4; ++jj) {
                float lo, hi;
                unpack2(acc2[i][jj], lo, hi);
                lo = alph[2 * jj]     * tanh_fast(lo * sfac[2 * jj]);
                hi = alph[2 * jj + 1] * tanh_fast(hi * sfac[2 * jj + 1]);
                acc2[i][jj] = pack2(lo, hi);
            }

        __syncthreads();                       // done reading xs/Ws/vectors
        store_tile2(xs, row, col, acc2);
        if (t < 4) {
            load_layer(Ws, sB, sS, sA,
                       Wh + t * HD * HD, bh + t * HD,
                       &g_S[(b * NL + t + 1) * HD], alpha + (t + 1) * HD, tid);
        } else {
            load_layer(Ws, sB, sS, sA, Wf, bf, nullptr, nullptr, tid);
        }
        __syncthreads();
    }

    // ---- final trunk layer: YL = x @ Wf + bf (no activation) ----
    {
#pragma unroll
        for (int jj = 0; jj < 4; ++jj) {
            unsigned long long bp = pack2(sB[col + 2 * jj], sB[col + 2 * jj + 1]);
#pragma unroll
            for (int i = 0; i < 8; ++i) acc2[i][jj] = bp;
        }
        matmul_tile2(xs, Ws, row, col, acc2);
        __syncthreads();
        store_tile2(xs, row, col, acc2);       // xs now holds YL
        __syncthreads();
    }

    // ---- output einsum: out[b,n,o] = sum_h ZL[b,o,h] * YL[n,h] ----
    for (int idx = tid; idx < nv * NO; idx += 128) {
        int p = idx / NO;
        int o = idx - p * NO;
        const float* zp = sZ + o * HD;
        const float* yp = xs + p * LDX;
        float s = 0.f;
#pragma unroll 16
        for (int h = 0; h < HD; ++h) s = fmaf(zp[h], yp[h], s);
        out[((long)b * NPTS + n0 + p) * NO + o] = s;
    }
}

// ---------------------------------------------------------------------------
// Launch
// ---------------------------------------------------------------------------
extern "C" void kernel_launch(void* const* d_in, const int* in_sizes, int n_in,
                              void* d_out, int out_size)
{
    const float* coords = (const float*)d_in[0];
    const float* params = (const float*)d_in[1];
    const float* bW0    = (const float*)d_in[2];
    const float* bb0    = (const float*)d_in[3];
    const float* bWh    = (const float*)d_in[4];
    const float* bbh    = (const float*)d_in[5];
    const float* balpha = (const float*)d_in[6];
    const float* bWf    = (const float*)d_in[7];
    const float* bbf    = (const float*)d_in[8];
    const float* tW0    = (const float*)d_in[9];
    const float* tb0    = (const float*)d_in[10];
    const float* tWh    = (const float*)d_in[11];
    const float* tbh    = (const float*)d_in[12];
    const float* talpha = (const float*)d_in[13];
    const float* tWf    = (const float*)d_in[14];
    const float* tbf    = (const float*)d_in[15];
    float* out = (float*)d_out;

    constexpr int SMEM_FLOATS =
        TILE_N * LDX + HD * HD + 3 * HD + NO * HD + TILE_N * 3;
    constexpr size_t SMEM_BYTES = SMEM_FLOATS * sizeof(float);

    cudaFuncSetAttribute(trunk_kernel,
                         cudaFuncAttributeMaxDynamicSharedMemorySize,
                         (int)SMEM_BYTES);

    branch_kernel<<<NB, HD>>>(params, bW0, bb0, bWh, bbh, balpha, bWf, bbf);

    dim3 grid((NPTS + TILE_N - 1) / TILE_N, NB);
    trunk_kernel<<<grid, 128, SMEM_BYTES>>>(coords, tW0, tb0, tWh, tbh,
                                            talpha, tWf, tbf, out);
}

// round 4
// speedup vs baseline: 4.5728x; 3.0894x over previous
#include <cuda_runtime.h>
#include <cuda_bf16.h>
#include <stdint.h>
#include <math.h>

#define NB     16
#define NPTS   50000
#define HD     128
#define NL     5
#define NO     5
#define PDIM   8
#define TILE_M 128
#define NTILES ((NPTS + TILE_M - 1) / TILE_M)
#define LDW    136   // bf16 elems per padded weight row (272B) -> conflict-free ldmatrix

// global scratch (allocation-free per harness rules)
__device__ float g_S [NB * NL * HD];                       // FiLM cumsums [b][l][h]
__device__ float g_ZL[NB * NO * HD];                       // branch out  [b][o][h]
__device__ __align__(16) __nv_bfloat16 g_Wb[5 * 2 * HD * LDW]; // [layer][hi|lo][n][LDW]

// smem layout (bytes)
#define WBUF_BYTES (2 * HD * LDW * 2)              // hi+lo planes = 69632
#define OFF_WBUF 0                                 // 2 buffers
#define OFF_W0   (2 * WBUF_BYTES)                  // 139264 : 3*128 f32
#define OFF_B0   (OFF_W0 + 3 * HD * 4)
#define OFF_BIAS (OFF_B0 + HD * 4)                 // 5*128 f32 (bh0..3, bf)
#define OFF_S    (OFF_BIAS + 5 * HD * 4)           // 5*128
#define OFF_ALPH (OFF_S + 5 * HD * 4)              // 5*128
#define OFF_Z    (OFF_ALPH + 5 * HD * 4)           // 5*128
#define OFF_C    (OFF_Z + 5 * HD * 4)              // 128*3
#define SMEM_TOTAL (OFF_C + TILE_M * 3 * 4)        // 153088

// ---------------- helpers ----------------
__device__ __forceinline__ float tanh_fast(float x) {
    float t; asm("tanh.approx.f32 %0, %1;" : "=f"(t) : "f"(x)); return t;
}
__device__ __forceinline__ void split2(float x, unsigned short& h, unsigned short& l) {
    __nv_bfloat16 hb = __float2bfloat16(x);
    float r = x - __bfloat162float(hb);
    __nv_bfloat16 lb = __float2bfloat16(r);
    h = __bfloat16_as_ushort(hb);
    l = __bfloat16_as_ushort(lb);
}
// pack pair (v0 -> low half, v1 -> high half) of bf16, and the bf16 residual pair
__device__ __forceinline__ void split_pair(float v0, float v1, uint32_t& hi2, uint32_t& lo2) {
    asm("cvt.rn.bf16x2.f32 %0, %1, %2;" : "=r"(hi2) : "f"(v1), "f"(v0));
    float h0 = __uint_as_float(hi2 << 16);
    float h1 = __uint_as_float(hi2 & 0xffff0000u);
    float r0 = v0 - h0, r1 = v1 - h1;
    asm("cvt.rn.bf16x2.f32 %0, %1, %2;" : "=r"(lo2) : "f"(r1), "f"(r0));
}
__device__ __forceinline__ uint32_t s2u(const void* p) {
    uint32_t a;
    asm("{ .reg .u64 t; cvta.to.shared.u64 t, %1; cvt.u32.u64 %0, t; }" : "=r"(a) : "l"(p));
    return a;
}
__device__ __forceinline__ void ldmatrix4(uint32_t& r0, uint32_t& r1, uint32_t& r2,
                                          uint32_t& r3, uint32_t addr) {
    asm volatile("ldmatrix.sync.aligned.m8n8.x4.shared.b16 {%0,%1,%2,%3}, [%4];"
                 : "=r"(r0), "=r"(r1), "=r"(r2), "=r"(r3) : "r"(addr));
}
__device__ __forceinline__ void mma_bf16(float& d0, float& d1, float& d2, float& d3,
                                         uint32_t a0, uint32_t a1, uint32_t a2, uint32_t a3,
                                         uint32_t b0, uint32_t b1) {
    asm volatile("mma.sync.aligned.m16n8k16.row.col.f32.bf16.bf16.f32 "
                 "{%0,%1,%2,%3}, {%4,%5,%6,%7}, {%8,%9}, {%0,%1,%2,%3};"
                 : "+f"(d0), "+f"(d1), "+f"(d2), "+f"(d3)
                 : "r"(a0), "r"(a1), "r"(a2), "r"(a3), "r"(b0), "r"(b1));
}
__device__ __forceinline__ void cp_async16(uint32_t saddr, const void* gptr) {
    asm volatile("cp.async.cg.shared.global [%0], [%1], 16;" :: "r"(saddr), "l"(gptr));
}
__device__ __forceinline__ void cp_commit() { asm volatile("cp.async.commit_group;" ::: "memory"); }
__device__ __forceinline__ void cp_wait0()  { asm volatile("cp.async.wait_group 0;"  ::: "memory"); }

// ---------------------------------------------------------------------------
// Prep: transpose trunk weights, bf16 hi/lo split -> [layer][plane][n][LDW]
// ---------------------------------------------------------------------------
__global__ void prep_weights(const float* __restrict__ Wh, const float* __restrict__ Wf)
{
    const int t = blockIdx.x;                       // 0..3: Wh[t], 4: Wf
    const float* W = (t < 4) ? (Wh + t * HD * HD) : Wf;
    __nv_bfloat16* hi = g_Wb + (size_t)t * 2 * HD * LDW;
    __nv_bfloat16* lo = hi + HD * LDW;
    for (int idx = threadIdx.x; idx < HD * HD; idx += blockDim.x) {
        int n = idx >> 7, k = idx & 127;
        unsigned short h, l;
        split2(W[k * HD + n], h, l);                // Wt[n][k] = W[k][n]
        hi[n * LDW + k] = __ushort_as_bfloat16(h);
        lo[n * LDW + k] = __ushort_as_bfloat16(l);
    }
}

// ---------------------------------------------------------------------------
// Branch MLP (exact tanhf): writes g_S and g_ZL (fp32)
// ---------------------------------------------------------------------------
__global__ void branch_kernel(const float* __restrict__ params,
                              const float* __restrict__ W0,
                              const float* __restrict__ b0,
                              const float* __restrict__ Wh,
                              const float* __restrict__ bh,
                              const float* __restrict__ alpha,
                              const float* __restrict__ Wf,
                              const float* __restrict__ bf)
{
    const int b = blockIdx.x;
    const int j = threadIdx.x;
    __shared__ float hs[HD];
    __shared__ float ps[PDIM];
    if (j < PDIM) ps[j] = params[b * PDIM + j];
    __syncthreads();

    float acc = b0[j];
#pragma unroll
    for (int k = 0; k < PDIM; ++k) acc = fmaf(ps[k], W0[k * HD + j], acc);
    float hv = alpha[j] * tanhf(acc);
    float S = hv;
    g_S[(b * NL + 0) * HD + j] = S;

    for (int i = 0; i < NL - 1; ++i) {
        hs[j] = hv;
        __syncthreads();
        float a2 = bh[i * HD + j];
#pragma unroll 8
        for (int k = 0; k < HD; ++k)
            a2 = fmaf(hs[k], Wh[(i * HD + k) * HD + j], a2);
        hv = alpha[(i + 1) * HD + j] * tanhf(a2);
        S += hv;
        g_S[(b * NL + i + 1) * HD + j] = S;
        __syncthreads();
    }

    hs[j] = hv;
    __syncthreads();
#pragma unroll
    for (int o = 0; o < NO; ++o) {
        float a2 = bf[o * HD + j];
#pragma unroll 8
        for (int k = 0; k < HD; ++k)
            a2 = fmaf(hs[k], Wf[k * (HD * NO) + o * HD + j], a2);
        g_ZL[(b * NO + o) * HD + j] = a2;
    }
}

// ---------------------------------------------------------------------------
// One 128x128 (x128 pts per CTA) bf16-split GEMM layer via mma.sync.
// A (hi/lo) in registers; B (hi/lo) from smem via ldmatrix.
// ---------------------------------------------------------------------------
__device__ __forceinline__ void mma_layer(float (&d)[16][4],
                                          const uint32_t (&ah)[32],
                                          const uint32_t (&al)[32],
                                          uint32_t wbase, int lane)
{
    const uint32_t hi_base = wbase;
    const uint32_t lo_base = wbase + HD * LDW * 2;
    const int grp  = lane >> 3;
    const int nrow = (lane & 7) + ((grp >> 1) << 3);   // + p*16
    const int kcol = (grp & 1) << 3;                   // + j*16
#pragma unroll
    for (int j = 0; j < 8; ++j) {
#pragma unroll
        for (int p = 0; p < 8; ++p) {
            uint32_t off = (uint32_t)(((nrow + p * 16) * LDW + kcol + j * 16) * 2);
            uint32_t bh0, bh1, bh2, bh3, bl0, bl1, bl2, bl3;
            ldmatrix4(bh0, bh1, bh2, bh3, hi_base + off);
            ldmatrix4(bl0, bl1, bl2, bl3, lo_base + off);
            // nt = 2p
            mma_bf16(d[2*p][0], d[2*p][1], d[2*p][2], d[2*p][3],
                     ah[4*j], ah[4*j+1], ah[4*j+2], ah[4*j+3], bh0, bh1);
            mma_bf16(d[2*p][0], d[2*p][1], d[2*p][2], d[2*p][3],
                     al[4*j], al[4*j+1], al[4*j+2], al[4*j+3], bh0, bh1);
            mma_bf16(d[2*p][0], d[2*p][1], d[2*p][2], d[2*p][3],
                     ah[4*j], ah[4*j+1], ah[4*j+2], ah[4*j+3], bl0, bl1);
            // nt = 2p+1
            mma_bf16(d[2*p+1][0], d[2*p+1][1], d[2*p+1][2], d[2*p+1][3],
                     ah[4*j], ah[4*j+1], ah[4*j+2], ah[4*j+3], bh2, bh3);
            mma_bf16(d[2*p+1][0], d[2*p+1][1], d[2*p+1][2], d[2*p+1][3],
                     al[4*j], al[4*j+1], al[4*j+2], al[4*j+3], bh2, bh3);
            mma_bf16(d[2*p+1][0], d[2*p+1][1], d[2*p+1][2], d[2*p+1][3],
                     ah[4*j], ah[4*j+1], ah[4*j+2], ah[4*j+3], bl2, bl3);
        }
    }
}

// ---------------------------------------------------------------------------
// Trunk: warp = 16 points x 128 features, activations resident in registers.
// 256 threads (8 warps) per CTA = 128 points; weights double-buffered in smem.
// ---------------------------------------------------------------------------
__global__ void __launch_bounds__(256, 1)
trunk_kernel(const float* __restrict__ coords,
             const float* __restrict__ tW0,
             const float* __restrict__ tb0,
             const float* __restrict__ tbh,
             const float* __restrict__ talpha,
             const float* __restrict__ tbf,
             float* __restrict__ out)
{
    extern __shared__ char sm[];
    const uint32_t sbase = s2u(sm);
    const int b    = blockIdx.y;
    const int n0   = blockIdx.x * TILE_M;
    const int nv   = min(TILE_M, NPTS - n0);
    const int tid  = threadIdx.x;
    const int lane = tid & 31;
    const int warp = tid >> 5;
    const int q    = lane & 3;
    const int g4   = lane >> 2;

    float* sW0 = (float*)(sm + OFF_W0);
    float* sB0 = (float*)(sm + OFF_B0);
    float* sBias = (float*)(sm + OFF_BIAS);
    float* sS  = (float*)(sm + OFF_S);
    float* sAl = (float*)(sm + OFF_ALPH);
    float* sZ  = (float*)(sm + OFF_Z);
    float* sC  = (float*)(sm + OFF_C);

    // ---- prologue: async-load layer-0 weights into buf0, plus misc ----
    {
        const char* src = (const char*)g_Wb;
        uint32_t dst = sbase + OFF_WBUF;
#pragma unroll
        for (int i = tid; i < WBUF_BYTES / 16; i += 256)
            cp_async16(dst + i * 16, src + i * 16);
        cp_commit();
    }
    for (int i = tid; i < 3 * HD; i += 256) sW0[i] = tW0[i];
    for (int i = tid; i < HD; i += 256)     sB0[i] = tb0[i];
    for (int i = tid; i < 4 * HD; i += 256) sBias[i] = tbh[i];
    for (int i = tid; i < HD; i += 256)     sBias[4 * HD + i] = tbf[i];
    for (int i = tid; i < NL * HD; i += 256) {
        sS[i]  = g_S[b * NL * HD + i];
        sAl[i] = talpha[i];
        sZ[i]  = g_ZL[b * NL * HD + i];      // NO==NL==5
    }
    for (int i = tid; i < TILE_M * 3; i += 256)
        sC[i] = (i < nv * 3) ? coords[((size_t)b * NPTS + n0) * 3 + i] : 0.f;
    cp_wait0();
    __syncthreads();

    uint32_t ah[32], al[32];
    const int mlo = warp * 16 + g4;         // local row (point) index
    const int mhi = mlo + 8;

    // ---- entry layer: coords(3) -> H, FiLM-tanh, split into A frags ----
    {
        float cl0 = sC[mlo * 3], cl1 = sC[mlo * 3 + 1], cl2 = sC[mlo * 3 + 2];
        float ch0 = sC[mhi * 3], ch1 = sC[mhi * 3 + 1], ch2 = sC[mhi * 3 + 2];
#pragma unroll
        for (int nt = 0; nt < 16; ++nt) {
            int c = nt * 8 + q * 2;
            float2 w0 = *(const float2*)&sW0[c];
            float2 w1 = *(const float2*)&sW0[HD + c];
            float2 w2 = *(const float2*)&sW0[2 * HD + c];
            float2 bb = *(const float2*)&sB0[c];
            float2 ss = *(const float2*)&sS[c];
            float2 aa = *(const float2*)&sAl[c];
            float v00 = bb.x + cl0 * w0.x + cl1 * w1.x + cl2 * w2.x;
            float v01 = bb.y + cl0 * w0.y + cl1 * w1.y + cl2 * w2.y;
            float v10 = bb.x + ch0 * w0.x + ch1 * w1.x + ch2 * w2.x;
            float v11 = bb.y + ch0 * w0.y + ch1 * w1.y + ch2 * w2.y;
            v00 = aa.x * tanh_fast(v00 * ss.x);
            v01 = aa.y * tanh_fast(v01 * ss.y);
            v10 = aa.x * tanh_fast(v10 * ss.x);
            v11 = aa.y * tanh_fast(v11 * ss.y);
            int base = 4 * (nt >> 1) + (nt & 1) * 2;
            split_pair(v00, v01, ah[base + 0], al[base + 0]);   // row-lo
            split_pair(v10, v11, ah[base + 1], al[base + 1]);   // row-hi
        }
    }

    // ---- weight layers 0..3 (Wh) with activation epilogue ----
#pragma unroll 1
    for (int g = 0; g < 4; ++g) {
        // prefetch next layer weights into the other buffer
        {
            const char* src = (const char*)g_Wb + (size_t)(g + 1) * WBUF_BYTES;
            uint32_t dst = sbase + OFF_WBUF + (uint32_t)(((g + 1) & 1) * WBUF_BYTES);
#pragma unroll
            for (int i = tid; i < WBUF_BYTES / 16; i += 256)
                cp_async16(dst + i * 16, src + i * 16);
            cp_commit();
        }

        float d[16][4];
#pragma unroll
        for (int nt = 0; nt < 16; ++nt)
#pragma unroll
            for (int r = 0; r < 4; ++r) d[nt][r] = 0.f;

        mma_layer(d, ah, al, sbase + OFF_WBUF + (uint32_t)((g & 1) * WBUF_BYTES), lane);

        const float* bias = sBias + g * HD;
        const float* Sv   = sS  + (g + 1) * HD;
        const float* Av   = sAl + (g + 1) * HD;
#pragma unroll
        for (int nt = 0; nt < 16; ++nt) {
            int c = nt * 8 + q * 2;
            float2 bb = *(const float2*)&bias[c];
            float2 ss = *(const float2*)&Sv[c];
            float2 aa = *(const float2*)&Av[c];
            float v00 = aa.x * tanh_fast((d[nt][0] + bb.x) * ss.x);
            float v01 = aa.y * tanh_fast((d[nt][1] + bb.y) * ss.y);
            float v10 = aa.x * tanh_fast((d[nt][2] + bb.x) * ss.x);
            float v11 = aa.y * tanh_fast((d[nt][3] + bb.y) * ss.y);
            int base = 4 * (nt >> 1) + (nt & 1) * 2;
            split_pair(v00, v01, ah[base + 0], al[base + 0]);
            split_pair(v10, v11, ah[base + 1], al[base + 1]);
        }

        cp_wait0();
        __syncthreads();    // buf[(g+1)&1] ready; all reads of buf[g&1] done
    }

    // ---- final layer (Wf) + output einsum ----
    {
        float d[16][4];
#pragma unroll
        for (int nt = 0; nt < 16; ++nt)
#pragma unroll
            for (int r = 0; r < 4; ++r) d[nt][r] = 0.f;

        mma_layer(d, ah, al, sbase + OFF_WBUF, lane);   // layer 4 in buf0

        const float* bias = sBias + 4 * HD;
        float po[2][NO];
#pragma unroll
        for (int h = 0; h < 2; ++h)
#pragma unroll
            for (int o = 0; o < NO; ++o) po[h][o] = 0.f;

#pragma unroll
        for (int nt = 0; nt < 16; ++nt) {
            int c = nt * 8 + q * 2;
            float2 bb = *(const float2*)&bias[c];
            float y00 = d[nt][0] + bb.x, y01 = d[nt][1] + bb.y;
            float y10 = d[nt][2] + bb.x, y11 = d[nt][3] + bb.y;
#pragma unroll
            for (int o = 0; o < NO; ++o) {
                float2 z = *(const float2*)&sZ[o * HD + c];
                po[0][o] = fmaf(y00, z.x, fmaf(y01, z.y, po[0][o]));
                po[1][o] = fmaf(y10, z.x, fmaf(y11, z.y, po[1][o]));
            }
        }
        // reduce across the 4 lanes of each quad
#pragma unroll
        for (int h = 0; h < 2; ++h)
#pragma unroll
            for (int o = 0; o < NO; ++o) {
                po[h][o] += __shfl_xor_sync(0xffffffffu, po[h][o], 1);
                po[h][o] += __shfl_xor_sync(0xffffffffu, po[h][o], 2);
            }
        if (q == 0) {
            if (mlo < nv) {
                float* op = out + ((size_t)b * NPTS + n0 + mlo) * NO;
#pragma unroll
                for (int o = 0; o < NO; ++o) op[o] = po[0][o];
            }
            if (mhi < nv) {
                float* op = out + ((size_t)b * NPTS + n0 + mhi) * NO;
#pragma unroll
                for (int o = 0; o < NO; ++o) op[o] = po[1][o];
            }
        }
    }
}

// ---------------------------------------------------------------------------
// Launch
// ---------------------------------------------------------------------------
extern "C" void kernel_launch(void* const* d_in, const int* in_sizes, int n_in,
                              void* d_out, int out_size)
{
    const float* coords = (const float*)d_in[0];
    const float* params = (const float*)d_in[1];
    const float* bW0    = (const float*)d_in[2];
    const float* bb0    = (const float*)d_in[3];
    const float* bWh    = (const float*)d_in[4];
    const float* bbh    = (const float*)d_in[5];
    const float* balpha = (const float*)d_in[6];
    const float* bWf    = (const float*)d_in[7];
    const float* bbf    = (const float*)d_in[8];
    const float* tW0    = (const float*)d_in[9];
    const float* tb0    = (const float*)d_in[10];
    const float* tWh    = (const float*)d_in[11];
    const float* tbh    = (const float*)d_in[12];
    const float* talpha = (const float*)d_in[13];
    const float* tWf    = (const float*)d_in[14];
    const float* tbf    = (const float*)d_in[15];
    float* out = (float*)d_out;

    cudaFuncSetAttribute(trunk_kernel,
                         cudaFuncAttributeMaxDynamicSharedMemorySize, SMEM_TOTAL);

    prep_weights<<<5, 256>>>(tWh, tWf);
    branch_kernel<<<NB, HD>>>(params, bW0, bb0, bWh, bbh, balpha, bWf, bbf);

    dim3 grid(NTILES, NB);
    trunk_kernel<<<grid, 256, SMEM_TOTAL>>>(coords, tW0, tb0, tbh, talpha, tbf, out);
}

// round 5
// speedup vs baseline: 5.9617x; 1.3037x over previous
#include <cuda_runtime.h>
#include <cuda_fp16.h>
#include <stdint.h>
#include <math.h>

#define NB     16
#define NPTS   50000
#define HD     128
#define NL     5
#define NO     5
#define PDIM   8
#define TILE_M 128
#define NTILES ((NPTS + TILE_M - 1) / TILE_M)
#define LDW    136   // fp16 elems per padded weight row (272B) -> conflict-free ldmatrix

// global scratch (allocation-free per harness rules)
__device__ float g_S [NB * NL * HD];                       // FiLM cumsums [b][l][h]
__device__ float g_ZL[NB * NO * HD];                       // branch out  [b][o][h]
__device__ __align__(16) __half g_Wb[5 * HD * LDW];        // [layer][n][LDW] fp16

// smem layout (bytes)
#define WBUF_BYTES (HD * LDW * 2)                  // single fp16 plane = 34816
#define OFF_WBUF 0                                 // 2 buffers (double-buffered)
#define OFF_W0   (2 * WBUF_BYTES)                  // 69632 : 3*128 f32
#define OFF_B0   (OFF_W0 + 3 * HD * 4)
#define OFF_BIAS (OFF_B0 + HD * 4)                 // 5*128 f32 (bh0..3, bf)
#define OFF_S    (OFF_BIAS + 5 * HD * 4)           // 5*128
#define OFF_ALPH (OFF_S + 5 * HD * 4)              // 5*128
#define OFF_Z    (OFF_ALPH + 5 * HD * 4)           // 5*128
#define OFF_C    (OFF_Z + 5 * HD * 4)              // 128*3
#define SMEM_TOTAL (OFF_C + TILE_M * 3 * 4)        // 83456

// ---------------- helpers ----------------
__device__ __forceinline__ float tanh_fast(float x) {
    float t; asm("tanh.approx.f32 %0, %1;" : "=f"(t) : "f"(x)); return t;
}
// fp16 hi/lo split of a pair: hi2 = {f16(v0), f16(v1)}, lo2 = residuals
__device__ __forceinline__ void split_pair(float v0, float v1, uint32_t& hi2, uint32_t& lo2) {
    __half2 h = __floats2half2_rn(v0, v1);         // .x = v0 (low), .y = v1 (high)
    float2 back = __half22float2(h);
    __half2 l = __floats2half2_rn(v0 - back.x, v1 - back.y);
    hi2 = *(uint32_t*)&h;
    lo2 = *(uint32_t*)&l;
}
__device__ __forceinline__ uint32_t s2u(const void* p) {
    uint32_t a;
    asm("{ .reg .u64 t; cvta.to.shared.u64 t, %1; cvt.u32.u64 %0, t; }" : "=r"(a) : "l"(p));
    return a;
}
__device__ __forceinline__ void ldmatrix4(uint32_t& r0, uint32_t& r1, uint32_t& r2,
                                          uint32_t& r3, uint32_t addr) {
    asm volatile("ldmatrix.sync.aligned.m8n8.x4.shared.b16 {%0,%1,%2,%3}, [%4];"
                 : "=r"(r0), "=r"(r1), "=r"(r2), "=r"(r3) : "r"(addr));
}
__device__ __forceinline__ void mma_f16(float& d0, float& d1, float& d2, float& d3,
                                        uint32_t a0, uint32_t a1, uint32_t a2, uint32_t a3,
                                        uint32_t b0, uint32_t b1) {
    asm volatile("mma.sync.aligned.m16n8k16.row.col.f32.f16.f16.f32 "
                 "{%0,%1,%2,%3}, {%4,%5,%6,%7}, {%8,%9}, {%0,%1,%2,%3};"
                 : "+f"(d0), "+f"(d1), "+f"(d2), "+f"(d3)
                 : "r"(a0), "r"(a1), "r"(a2), "r"(a3), "r"(b0), "r"(b1));
}
__device__ __forceinline__ void cp_async16(uint32_t saddr, const void* gptr) {
    asm volatile("cp.async.cg.shared.global [%0], [%1], 16;" :: "r"(saddr), "l"(gptr));
}
__device__ __forceinline__ void cp_commit() { asm volatile("cp.async.commit_group;" ::: "memory"); }
__device__ __forceinline__ void cp_wait0()  { asm volatile("cp.async.wait_group 0;"  ::: "memory"); }

// ---------------------------------------------------------------------------
// Prep: transpose trunk weights -> fp16 [layer][n][LDW]; 8 blocks per layer
// ---------------------------------------------------------------------------
__global__ void prep_weights(const float* __restrict__ Wh, const float* __restrict__ Wf)
{
    const int t     = blockIdx.x >> 3;              // 0..3: Wh[t], 4: Wf
    const int slice = blockIdx.x & 7;               // 16 n-rows per slice
    const float* W = (t < 4) ? (Wh + t * HD * HD) : Wf;
    __half* dst = g_Wb + (size_t)t * HD * LDW;
    for (int idx = threadIdx.x; idx < 16 * HD; idx += blockDim.x) {
        int n = slice * 16 + (idx & 15);
        int k = idx >> 4;
        dst[n * LDW + k] = __float2half_rn(W[k * HD + n]);   // Wt[n][k] = W[k][n]
    }
}

// ---------------------------------------------------------------------------
// Branch MLP (exact tanhf): writes g_S and g_ZL (fp32)
// ---------------------------------------------------------------------------
__global__ void branch_kernel(const float* __restrict__ params,
                              const float* __restrict__ W0,
                              const float* __restrict__ b0,
                              const float* __restrict__ Wh,
                              const float* __restrict__ bh,
                              const float* __restrict__ alpha,
                              const float* __restrict__ Wf,
                              const float* __restrict__ bf)
{
    const int b = blockIdx.x;
    const int j = threadIdx.x;
    __shared__ float hs[HD];
    __shared__ float ps[PDIM];
    if (j < PDIM) ps[j] = params[b * PDIM + j];
    __syncthreads();

    float acc = b0[j];
#pragma unroll
    for (int k = 0; k < PDIM; ++k) acc = fmaf(ps[k], W0[k * HD + j], acc);
    float hv = alpha[j] * tanhf(acc);
    float S = hv;
    g_S[(b * NL + 0) * HD + j] = S;

    for (int i = 0; i < NL - 1; ++i) {
        hs[j] = hv;
        __syncthreads();
        float a2 = bh[i * HD + j];
#pragma unroll 8
        for (int k = 0; k < HD; ++k)
            a2 = fmaf(hs[k], Wh[(i * HD + k) * HD + j], a2);
        hv = alpha[(i + 1) * HD + j] * tanhf(a2);
        S += hv;
        g_S[(b * NL + i + 1) * HD + j] = S;
        __syncthreads();
    }

    hs[j] = hv;
    __syncthreads();
#pragma unroll
    for (int o = 0; o < NO; ++o) {
        float a2 = bf[o * HD + j];
#pragma unroll 8
        for (int k = 0; k < HD; ++k)
            a2 = fmaf(hs[k], Wf[k * (HD * NO) + o * HD + j], a2);
        g_ZL[(b * NO + o) * HD + j] = a2;
    }
}

// ---------------------------------------------------------------------------
// One 128x128 GEMM layer via mma.sync, fp16 2-product (A hi+lo, B single).
// ---------------------------------------------------------------------------
__device__ __forceinline__ void mma_layer(float (&d)[16][4],
                                          const uint32_t (&ah)[32],
                                          const uint32_t (&al)[32],
                                          uint32_t wbase, int lane)
{
    const int grp  = lane >> 3;
    const int nrow = (lane & 7) + ((grp >> 1) << 3);   // + p*16
    const int kcol = (grp & 1) << 3;                   // + j*16
#pragma unroll
    for (int j = 0; j < 8; ++j) {
#pragma unroll
        for (int p = 0; p < 8; ++p) {
            uint32_t off = (uint32_t)(((nrow + p * 16) * LDW + kcol + j * 16) * 2);
            uint32_t b0, b1, b2, b3;
            ldmatrix4(b0, b1, b2, b3, wbase + off);
            // nt = 2p
            mma_f16(d[2*p][0], d[2*p][1], d[2*p][2], d[2*p][3],
                    ah[4*j], ah[4*j+1], ah[4*j+2], ah[4*j+3], b0, b1);
            mma_f16(d[2*p][0], d[2*p][1], d[2*p][2], d[2*p][3],
                    al[4*j], al[4*j+1], al[4*j+2], al[4*j+3], b0, b1);
            // nt = 2p+1
            mma_f16(d[2*p+1][0], d[2*p+1][1], d[2*p+1][2], d[2*p+1][3],
                    ah[4*j], ah[4*j+1], ah[4*j+2], ah[4*j+3], b2, b3);
            mma_f16(d[2*p+1][0], d[2*p+1][1], d[2*p+1][2], d[2*p+1][3],
                    al[4*j], al[4*j+1], al[4*j+2], al[4*j+3], b2, b3);
        }
    }
}

// ---------------------------------------------------------------------------
// Trunk: warp = 16 points x 128 features, activations resident in registers.
// 256 threads (8 warps) per CTA = 128 points; weights double-buffered in smem.
// ---------------------------------------------------------------------------
__global__ void __launch_bounds__(256, 1)
trunk_kernel(const float* __restrict__ coords,
             const float* __restrict__ tW0,
             const float* __restrict__ tb0,
             const float* __restrict__ tbh,
             const float* __restrict__ talpha,
             const float* __restrict__ tbf,
             float* __restrict__ out)
{
    extern __shared__ char sm[];
    const uint32_t sbase = s2u(sm);
    const int b    = blockIdx.y;
    const int n0   = blockIdx.x * TILE_M;
    const int nv   = min(TILE_M, NPTS - n0);
    const int tid  = threadIdx.x;
    const int lane = tid & 31;
    const int warp = tid >> 5;
    const int q    = lane & 3;
    const int g4   = lane >> 2;

    float* sW0 = (float*)(sm + OFF_W0);
    float* sB0 = (float*)(sm + OFF_B0);
    float* sBias = (float*)(sm + OFF_BIAS);
    float* sS  = (float*)(sm + OFF_S);
    float* sAl = (float*)(sm + OFF_ALPH);
    float* sZ  = (float*)(sm + OFF_Z);
    float* sC  = (float*)(sm + OFF_C);

    // ---- prologue: async-load layer-0 weights into buf0, plus misc ----
    {
        const char* src = (const char*)g_Wb;
        uint32_t dst = sbase + OFF_WBUF;
#pragma unroll
        for (int i = tid; i < WBUF_BYTES / 16; i += 256)
            cp_async16(dst + i * 16, src + i * 16);
        cp_commit();
    }
    for (int i = tid; i < 3 * HD; i += 256) sW0[i] = tW0[i];
    for (int i = tid; i < HD; i += 256)     sB0[i] = tb0[i];
    for (int i = tid; i < 4 * HD; i += 256) sBias[i] = tbh[i];
    for (int i = tid; i < HD; i += 256)     sBias[4 * HD + i] = tbf[i];
    for (int i = tid; i < NL * HD; i += 256) {
        sS[i]  = g_S[b * NL * HD + i];
        sAl[i] = talpha[i];
        sZ[i]  = g_ZL[b * NL * HD + i];      // NO==NL==5
    }
    for (int i = tid; i < TILE_M * 3; i += 256)
        sC[i] = (i < nv * 3) ? coords[((size_t)b * NPTS + n0) * 3 + i] : 0.f;
    cp_wait0();
    __syncthreads();

    uint32_t ah[32], al[32];
    const int mlo = warp * 16 + g4;         // local row (point) index
    const int mhi = mlo + 8;

    // ---- entry layer: coords(3) -> H, FiLM-tanh, split into A frags ----
    {
        float cl0 = sC[mlo * 3], cl1 = sC[mlo * 3 + 1], cl2 = sC[mlo * 3 + 2];
        float ch0 = sC[mhi * 3], ch1 = sC[mhi * 3 + 1], ch2 = sC[mhi * 3 + 2];
#pragma unroll
        for (int nt = 0; nt < 16; ++nt) {
            int c = nt * 8 + q * 2;
            float2 w0 = *(const float2*)&sW0[c];
            float2 w1 = *(const float2*)&sW0[HD + c];
            float2 w2 = *(const float2*)&sW0[2 * HD + c];
            float2 bb = *(const float2*)&sB0[c];
            float2 ss = *(const float2*)&sS[c];
            float2 aa = *(const float2*)&sAl[c];
            float v00 = bb.x + cl0 * w0.x + cl1 * w1.x + cl2 * w2.x;
            float v01 = bb.y + cl0 * w0.y + cl1 * w1.y + cl2 * w2.y;
            float v10 = bb.x + ch0 * w0.x + ch1 * w1.x + ch2 * w2.x;
            float v11 = bb.y + ch0 * w0.y + ch1 * w1.y + ch2 * w2.y;
            v00 = aa.x * tanh_fast(v00 * ss.x);
            v01 = aa.y * tanh_fast(v01 * ss.y);
            v10 = aa.x * tanh_fast(v10 * ss.x);
            v11 = aa.y * tanh_fast(v11 * ss.y);
            int base = 4 * (nt >> 1) + (nt & 1) * 2;
            split_pair(v00, v01, ah[base + 0], al[base + 0]);   // row-lo
            split_pair(v10, v11, ah[base + 1], al[base + 1]);   // row-hi
        }
    }

    // ---- weight layers 0..3 (Wh) with activation epilogue ----
#pragma unroll 1
    for (int g = 0; g < 4; ++g) {
        // prefetch next layer weights into the other buffer
        {
            const char* src = (const char*)g_Wb + (size_t)(g + 1) * WBUF_BYTES;
            uint32_t dst = sbase + OFF_WBUF + (uint32_t)(((g + 1) & 1) * WBUF_BYTES);
#pragma unroll
            for (int i = tid; i < WBUF_BYTES / 16; i += 256)
                cp_async16(dst + i * 16, src + i * 16);
            cp_commit();
        }

        float d[16][4];
#pragma unroll
        for (int nt = 0; nt < 16; ++nt)
#pragma unroll
            for (int r = 0; r < 4; ++r) d[nt][r] = 0.f;

        mma_layer(d, ah, al, sbase + OFF_WBUF + (uint32_t)((g & 1) * WBUF_BYTES), lane);

        const float* bias = sBias + g * HD;
        const float* Sv   = sS  + (g + 1) * HD;
        const float* Av   = sAl + (g + 1) * HD;
#pragma unroll
        for (int nt = 0; nt < 16; ++nt) {
            int c = nt * 8 + q * 2;
            float2 bb = *(const float2*)&bias[c];
            float2 ss = *(const float2*)&Sv[c];
            float2 aa = *(const float2*)&Av[c];
            float v00 = aa.x * tanh_fast((d[nt][0] + bb.x) * ss.x);
            float v01 = aa.y * tanh_fast((d[nt][1] + bb.y) * ss.y);
            float v10 = aa.x * tanh_fast((d[nt][2] + bb.x) * ss.x);
            float v11 = aa.y * tanh_fast((d[nt][3] + bb.y) * ss.y);
            int base = 4 * (nt >> 1) + (nt & 1) * 2;
            split_pair(v00, v01, ah[base + 0], al[base + 0]);
            split_pair(v10, v11, ah[base + 1], al[base + 1]);
        }

        cp_wait0();
        __syncthreads();    // buf[(g+1)&1] ready; all reads of buf[g&1] done
    }

    // ---- final layer (Wf) + output einsum ----
    {
        float d[16][4];
#pragma unroll
        for (int nt = 0; nt < 16; ++nt)
#pragma unroll
            for (int r = 0; r < 4; ++r) d[nt][r] = 0.f;

        mma_layer(d, ah, al, sbase + OFF_WBUF, lane);   // layer 4 in buf0

        const float* bias = sBias + 4 * HD;
        float po[2][NO];
#pragma unroll
        for (int h = 0; h < 2; ++h)
#pragma unroll
            for (int o = 0; o < NO; ++o) po[h][o] = 0.f;

#pragma unroll
        for (int nt = 0; nt < 16; ++nt) {
            int c = nt * 8 + q * 2;
            float2 bb = *(const float2*)&bias[c];
            float y00 = d[nt][0] + bb.x, y01 = d[nt][1] + bb.y;
            float y10 = d[nt][2] + bb.x, y11 = d[nt][3] + bb.y;
#pragma unroll
            for (int o = 0; o < NO; ++o) {
                float2 z = *(const float2*)&sZ[o * HD + c];
                po[0][o] = fmaf(y00, z.x, fmaf(y01, z.y, po[0][o]));
                po[1][o] = fmaf(y10, z.x, fmaf(y11, z.y, po[1][o]));
            }
        }
        // reduce across the 4 lanes of each quad
#pragma unroll
        for (int h = 0; h < 2; ++h)
#pragma unroll
            for (int o = 0; o < NO; ++o) {
                po[h][o] += __shfl_xor_sync(0xffffffffu, po[h][o], 1);
                po[h][o] += __shfl_xor_sync(0xffffffffu, po[h][o], 2);
            }
        if (q == 0) {
            if (mlo < nv) {
                float* op = out + ((size_t)b * NPTS + n0 + mlo) * NO;
#pragma unroll
                for (int o = 0; o < NO; ++o) op[o] = po[0][o];
            }
            if (mhi < nv) {
                float* op = out + ((size_t)b * NPTS + n0 + mhi) * NO;
#pragma unroll
                for (int o = 0; o < NO; ++o) op[o] = po[1][o];
            }
        }
    }
}

// ---------------------------------------------------------------------------
// Launch
// ---------------------------------------------------------------------------
extern "C" void kernel_launch(void* const* d_in, const int* in_sizes, int n_in,
                              void* d_out, int out_size)
{
    const float* coords = (const float*)d_in[0];
    const float* params = (const float*)d_in[1];
    const float* bW0    = (const float*)d_in[2];
    const float* bb0    = (const float*)d_in[3];
    const float* bWh    = (const float*)d_in[4];
    const float* bbh    = (const float*)d_in[5];
    const float* balpha = (const float*)d_in[6];
    const float* bWf    = (const float*)d_in[7];
    const float* bbf    = (const float*)d_in[8];
    const float* tW0    = (const float*)d_in[9];
    const float* tb0    = (const float*)d_in[10];
    const float* tWh    = (const float*)d_in[11];
    const float* tbh    = (const float*)d_in[12];
    const float* talpha = (const float*)d_in[13];
    const float* tWf    = (const float*)d_in[14];
    const float* tbf    = (const float*)d_in[15];
    float* out = (float*)d_out;

    cudaFuncSetAttribute(trunk_kernel,
                         cudaFuncAttributeMaxDynamicSharedMemorySize, SMEM_TOTAL);

    prep_weights<<<40, 256>>>(tWh, tWf);
    branch_kernel<<<NB, HD>>>(params, bW0, bb0, bWh, bbh, balpha, bWf, bbf);

    dim3 grid(NTILES, NB);
    trunk_kernel<<<grid, 256, SMEM_TOTAL>>>(coords, tW0, tb0, tbh, talpha, tbf, out);
}

// round 6
// speedup vs baseline: 9.1596x; 1.5364x over previous
#include <cuda_runtime.h>
#include <cuda_fp16.h>
#include <stdint.h>
#include <math.h>

#define NB     16
#define NPTS   50000
#define HD     128
#define NL     5
#define NO     5
#define PDIM   8
#define TILE_M 128
#define NTILES ((NPTS + TILE_M - 1) / TILE_M)
#define LDW    136   // fp16 elems per padded weight row (272B) -> conflict-free ldmatrix

// global scratch (allocation-free per harness rules)
__device__ float g_S [NB * NL * HD];                   // FiLM cumsums [b][l][h]
__device__ float g_bS[NB * NL * HD];                   // bias*S       [b][l][h]
__device__ float g_ZL[NB * NO * HD];                   // branch out   [b][o][h]
__device__ float g_zb[NB * NO];                        // sum_h ZL*bf  [b][o]
__device__ __align__(16) __half g_Wb[5 * HD * LDW];    // [layer][n][LDW] fp16, alpha-folded

// smem layout (bytes)
#define WBUF_BYTES (HD * LDW * 2)                  // 34816
#define OFF_WBUF 0                                 // 2 buffers
#define OFF_W0   (2 * WBUF_BYTES)                  // 69632 : 3*128 f32
#define OFF_S    (OFF_W0 + 3 * HD * 4)             // 5*128 f32
#define OFF_BS   (OFF_S + 5 * HD * 4)              // 5*128 f32
#define OFF_Z    (OFF_BS + 5 * HD * 4)             // 5*128 f32
#define OFF_ZB   (OFF_Z + 5 * HD * 4)              // 8 f32 (5 used)
#define OFF_C    (OFF_ZB + 8 * 4)                  // 128*3 f32
#define SMEM_TOTAL (OFF_C + TILE_M * 3 * 4)

// ---------------- helpers ----------------
__device__ __forceinline__ float tanh_fast(float x) {
    float t; asm("tanh.approx.f32 %0, %1;" : "=f"(t) : "f"(x)); return t;
}
__device__ __forceinline__ uint32_t pack_h2(float v0, float v1) {
    __half2 h = __floats2half2_rn(v0, v1);
    return *(uint32_t*)&h;
}
__device__ __forceinline__ uint32_t s2u(const void* p) {
    uint32_t a;
    asm("{ .reg .u64 t; cvta.to.shared.u64 t, %1; cvt.u32.u64 %0, t; }" : "=r"(a) : "l"(p));
    return a;
}
__device__ __forceinline__ void ldmatrix4(uint32_t& r0, uint32_t& r1, uint32_t& r2,
                                          uint32_t& r3, uint32_t addr) {
    asm volatile("ldmatrix.sync.aligned.m8n8.x4.shared.b16 {%0,%1,%2,%3}, [%4];"
                 : "=r"(r0), "=r"(r1), "=r"(r2), "=r"(r3) : "r"(addr));
}
__device__ __forceinline__ void mma_f16(float& d0, float& d1, float& d2, float& d3,
                                        uint32_t a0, uint32_t a1, uint32_t a2, uint32_t a3,
                                        uint32_t b0, uint32_t b1) {
    asm volatile("mma.sync.aligned.m16n8k16.row.col.f32.f16.f16.f32 "
                 "{%0,%1,%2,%3}, {%4,%5,%6,%7}, {%8,%9}, {%0,%1,%2,%3};"
                 : "+f"(d0), "+f"(d1), "+f"(d2), "+f"(d3)
                 : "r"(a0), "r"(a1), "r"(a2), "r"(a3), "r"(b0), "r"(b1));
}
__device__ __forceinline__ void cp_async16(uint32_t saddr, const void* gptr) {
    asm volatile("cp.async.cg.shared.global [%0], [%1], 16;" :: "r"(saddr), "l"(gptr));
}
__device__ __forceinline__ void cp_commit() { asm volatile("cp.async.commit_group;" ::: "memory"); }
__device__ __forceinline__ void cp_wait0()  { asm volatile("cp.async.wait_group 0;"  ::: "memory"); }

// ---------------------------------------------------------------------------
// Prep: transpose trunk weights, fold alpha into input rows -> fp16 planes
// Wh[t] consumes x scaled by alpha[t]; Wf consumes x scaled by alpha[4].
// ---------------------------------------------------------------------------
__global__ void prep_weights(const float* __restrict__ Wh, const float* __restrict__ Wf,
                             const float* __restrict__ alpha)
{
    const int t     = blockIdx.x >> 3;              // 0..3: Wh[t], 4: Wf
    const int slice = blockIdx.x & 7;               // 16 n-rows per slice
    const float* W = (t < 4) ? (Wh + t * HD * HD) : Wf;
    const float* al = alpha + t * HD;
    __half* dst = g_Wb + (size_t)t * HD * LDW;
    for (int idx = threadIdx.x; idx < 16 * HD; idx += blockDim.x) {
        int n = slice * 16 + (idx & 15);
        int k = idx >> 4;
        dst[n * LDW + k] = __float2half_rn(W[k * HD + n] * al[k]);
    }
}

// ---------------------------------------------------------------------------
// Branch MLP (exact tanhf): writes g_S, g_bS, g_ZL, g_zb
// ---------------------------------------------------------------------------
__global__ void branch_kernel(const float* __restrict__ params,
                              const float* __restrict__ W0,
                              const float* __restrict__ b0,
                              const float* __restrict__ Wh,
                              const float* __restrict__ bh,
                              const float* __restrict__ alpha,
                              const float* __restrict__ Wf,
                              const float* __restrict__ bf,
                              const float* __restrict__ tb0,
                              const float* __restrict__ tbh,
                              const float* __restrict__ tbf)
{
    const int b = blockIdx.x;
    const int j = threadIdx.x;
    __shared__ float hs[HD];
    __shared__ float ps[PDIM];
    if (j < PDIM) ps[j] = params[b * PDIM + j];
    __syncthreads();

    float acc = b0[j];
#pragma unroll
    for (int k = 0; k < PDIM; ++k) acc = fmaf(ps[k], W0[k * HD + j], acc);
    float hv = alpha[j] * tanhf(acc);
    float S = hv;
    g_S [(b * NL + 0) * HD + j] = S;
    g_bS[(b * NL + 0) * HD + j] = tb0[j] * S;

    for (int i = 0; i < NL - 1; ++i) {
        hs[j] = hv;
        __syncthreads();
        float a2 = bh[i * HD + j];
#pragma unroll 8
        for (int k = 0; k < HD; ++k)
            a2 = fmaf(hs[k], Wh[(i * HD + k) * HD + j], a2);
        hv = alpha[(i + 1) * HD + j] * tanhf(a2);
        S += hv;
        g_S [(b * NL + i + 1) * HD + j] = S;
        g_bS[(b * NL + i + 1) * HD + j] = tbh[i * HD + j] * S;
        __syncthreads();
    }

    hs[j] = hv;
    __syncthreads();

    float zl[NO];
#pragma unroll
    for (int o = 0; o < NO; ++o) {
        float a2 = bf[o * HD + j];
#pragma unroll 8
        for (int k = 0; k < HD; ++k)
            a2 = fmaf(hs[k], Wf[k * (HD * NO) + o * HD + j], a2);
        zl[o] = a2;
        g_ZL[(b * NO + o) * HD + j] = a2;
    }
    // zb[b][o] = sum_h ZL[b][o][h] * tbf[h]
    float tb = tbf[j];
    __syncthreads();
#pragma unroll
    for (int o = 0; o < NO; ++o) {
        hs[j] = zl[o] * tb;
        __syncthreads();
#pragma unroll
        for (int s = 64; s > 0; s >>= 1) {
            if (j < s) hs[j] += hs[j + s];
            __syncthreads();
        }
        if (j == 0) g_zb[b * NO + o] = hs[0];
        __syncthreads();
    }
}

// ---------------------------------------------------------------------------
// One 128x128 GEMM layer via mma.sync, single fp16 product.
// ---------------------------------------------------------------------------
__device__ __forceinline__ void mma_layer(float (&d)[16][4],
                                          const uint32_t (&ah)[32],
                                          uint32_t wbase, int lane)
{
    const int grp  = lane >> 3;
    const int nrow = (lane & 7) + ((grp >> 1) << 3);   // + p*16
    const int kcol = (grp & 1) << 3;                   // + j*16
#pragma unroll
    for (int j = 0; j < 8; ++j) {
#pragma unroll
        for (int p = 0; p < 8; ++p) {
            uint32_t off = (uint32_t)(((nrow + p * 16) * LDW + kcol + j * 16) * 2);
            uint32_t b0, b1, b2, b3;
            ldmatrix4(b0, b1, b2, b3, wbase + off);
            mma_f16(d[2*p][0], d[2*p][1], d[2*p][2], d[2*p][3],
                    ah[4*j], ah[4*j+1], ah[4*j+2], ah[4*j+3], b0, b1);
            mma_f16(d[2*p+1][0], d[2*p+1][1], d[2*p+1][2], d[2*p+1][3],
                    ah[4*j], ah[4*j+1], ah[4*j+2], ah[4*j+3], b2, b3);
        }
    }
}

// ---------------------------------------------------------------------------
// Trunk: warp = 16 points x 128 features, activations in registers (fp16).
// 256 threads (8 warps) per CTA = 128 points; weights double-buffered in smem.
// ---------------------------------------------------------------------------
__global__ void __launch_bounds__(256, 1)
trunk_kernel(const float* __restrict__ coords,
             const float* __restrict__ tW0,
             float* __restrict__ out)
{
    extern __shared__ char sm[];
    const uint32_t sbase = s2u(sm);
    const int b    = blockIdx.y;
    const int n0   = blockIdx.x * TILE_M;
    const int nv   = min(TILE_M, NPTS - n0);
    const int tid  = threadIdx.x;
    const int lane = tid & 31;
    const int warp = tid >> 5;
    const int q    = lane & 3;
    const int g4   = lane >> 2;

    float* sW0 = (float*)(sm + OFF_W0);
    float* sS  = (float*)(sm + OFF_S);
    float* sBS = (float*)(sm + OFF_BS);
    float* sZ  = (float*)(sm + OFF_Z);
    float* sZB = (float*)(sm + OFF_ZB);
    float* sC  = (float*)(sm + OFF_C);

    // ---- prologue: async-load layer-0 weights into buf0, plus misc ----
    {
        const char* src = (const char*)g_Wb;
        uint32_t dst = sbase + OFF_WBUF;
#pragma unroll
        for (int i = tid; i < WBUF_BYTES / 16; i += 256)
            cp_async16(dst + i * 16, src + i * 16);
        cp_commit();
    }
    for (int i = tid; i < 3 * HD; i += 256) sW0[i] = tW0[i];
    for (int i = tid; i < NL * HD; i += 256) {
        sS[i]  = g_S [b * NL * HD + i];
        sBS[i] = g_bS[b * NL * HD + i];
        sZ[i]  = g_ZL[b * NL * HD + i];      // NO==NL==5
    }
    if (tid < NO) sZB[tid] = g_zb[b * NO + tid];
    for (int i = tid; i < TILE_M * 3; i += 256)
        sC[i] = (i < nv * 3) ? coords[((size_t)b * NPTS + n0) * 3 + i] : 0.f;
    cp_wait0();
    __syncthreads();

    uint32_t ah[32];
    const int mlo = warp * 16 + g4;         // local row (point) index
    const int mhi = mlo + 8;

    // ---- entry layer: v = c@W0 ; x = tanh(v*S0 + b0*S0) (alpha0 folded) ----
    {
        float cl0 = sC[mlo * 3], cl1 = sC[mlo * 3 + 1], cl2 = sC[mlo * 3 + 2];
        float ch0 = sC[mhi * 3], ch1 = sC[mhi * 3 + 1], ch2 = sC[mhi * 3 + 2];
#pragma unroll
        for (int nt = 0; nt < 16; ++nt) {
            int c = nt * 8 + q * 2;
            float2 w0 = *(const float2*)&sW0[c];
            float2 w1 = *(const float2*)&sW0[HD + c];
            float2 w2 = *(const float2*)&sW0[2 * HD + c];
            float2 ss = *(const float2*)&sS[c];
            float2 bs = *(const float2*)&sBS[c];
            float v00 = cl0 * w0.x + cl1 * w1.x + cl2 * w2.x;
            float v01 = cl0 * w0.y + cl1 * w1.y + cl2 * w2.y;
            float v10 = ch0 * w0.x + ch1 * w1.x + ch2 * w2.x;
            float v11 = ch0 * w0.y + ch1 * w1.y + ch2 * w2.y;
            v00 = tanh_fast(fmaf(v00, ss.x, bs.x));
            v01 = tanh_fast(fmaf(v01, ss.y, bs.y));
            v10 = tanh_fast(fmaf(v10, ss.x, bs.x));
            v11 = tanh_fast(fmaf(v11, ss.y, bs.y));
            int base = 4 * (nt >> 1) + (nt & 1) * 2;
            ah[base + 0] = pack_h2(v00, v01);
            ah[base + 1] = pack_h2(v10, v11);
        }
    }

    // ---- hidden layers 0..3 (Wh', alpha-folded) ----
#pragma unroll 1
    for (int g = 0; g < 4; ++g) {
        // prefetch next layer weights into the other buffer
        {
            const char* src = (const char*)g_Wb + (size_t)(g + 1) * WBUF_BYTES;
            uint32_t dst = sbase + OFF_WBUF + (uint32_t)(((g + 1) & 1) * WBUF_BYTES);
#pragma unroll
            for (int i = tid; i < WBUF_BYTES / 16; i += 256)
                cp_async16(dst + i * 16, src + i * 16);
            cp_commit();
        }

        float d[16][4];
#pragma unroll
        for (int nt = 0; nt < 16; ++nt)
#pragma unroll
            for (int r = 0; r < 4; ++r) d[nt][r] = 0.f;

        mma_layer(d, ah, sbase + OFF_WBUF + (uint32_t)((g & 1) * WBUF_BYTES), lane);

        const float* Sv = sS  + (g + 1) * HD;
        const float* Bv = sBS + (g + 1) * HD;
#pragma unroll
        for (int nt = 0; nt < 16; ++nt) {
            int c = nt * 8 + q * 2;
            float2 ss = *(const float2*)&Sv[c];
            float2 bs = *(const float2*)&Bv[c];
            float v00 = tanh_fast(fmaf(d[nt][0], ss.x, bs.x));
            float v01 = tanh_fast(fmaf(d[nt][1], ss.y, bs.y));
            float v10 = tanh_fast(fmaf(d[nt][2], ss.x, bs.x));
            float v11 = tanh_fast(fmaf(d[nt][3], ss.y, bs.y));
            int base = 4 * (nt >> 1) + (nt & 1) * 2;
            ah[base + 0] = pack_h2(v00, v01);
            ah[base + 1] = pack_h2(v10, v11);
        }

        cp_wait0();
        __syncthreads();    // buf[(g+1)&1] ready; all reads of buf[g&1] done
    }

    // ---- final layer (Wf', alpha4-folded) + einsum (bf folded into zb) ----
    {
        float d[16][4];
#pragma unroll
        for (int nt = 0; nt < 16; ++nt)
#pragma unroll
            for (int r = 0; r < 4; ++r) d[nt][r] = 0.f;

        mma_layer(d, ah, sbase + OFF_WBUF, lane);   // layer 4 in buf0

        float po[2][NO];
#pragma unroll
        for (int h = 0; h < 2; ++h)
#pragma unroll
            for (int o = 0; o < NO; ++o) po[h][o] = 0.f;

#pragma unroll
        for (int nt = 0; nt < 16; ++nt) {
            int c = nt * 8 + q * 2;
#pragma unroll
            for (int o = 0; o < NO; ++o) {
                float2 z = *(const float2*)&sZ[o * HD + c];
                po[0][o] = fmaf(d[nt][0], z.x, fmaf(d[nt][1], z.y, po[0][o]));
                po[1][o] = fmaf(d[nt][2], z.x, fmaf(d[nt][3], z.y, po[1][o]));
            }
        }
        // reduce across the 4 lanes of each quad
#pragma unroll
        for (int h = 0; h < 2; ++h)
#pragma unroll
            for (int o = 0; o < NO; ++o) {
                po[h][o] += __shfl_xor_sync(0xffffffffu, po[h][o], 1);
                po[h][o] += __shfl_xor_sync(0xffffffffu, po[h][o], 2);
            }
        if (q == 0) {
            if (mlo < nv) {
                float* op = out + ((size_t)b * NPTS + n0 + mlo) * NO;
#pragma unroll
                for (int o = 0; o < NO; ++o) op[o] = po[0][o] + sZB[o];
            }
            if (mhi < nv) {
                float* op = out + ((size_t)b * NPTS + n0 + mhi) * NO;
#pragma unroll
                for (int o = 0; o < NO; ++o) op[o] = po[1][o] + sZB[o];
            }
        }
    }
}

// ---------------------------------------------------------------------------
// Launch
// ---------------------------------------------------------------------------
extern "C" void kernel_launch(void* const* d_in, const int* in_sizes, int n_in,
                              void* d_out, int out_size)
{
    const float* coords = (const float*)d_in[0];
    const float* params = (const float*)d_in[1];
    const float* bW0    = (const float*)d_in[2];
    const float* bb0    = (const float*)d_in[3];
    const float* bWh    = (const float*)d_in[4];
    const float* bbh    = (const float*)d_in[5];
    const float* balpha = (const float*)d_in[6];
    const float* bWf    = (const float*)d_in[7];
    const float* bbf    = (const float*)d_in[8];
    const float* tW0    = (const float*)d_in[9];
    const float* tb0    = (const float*)d_in[10];
    const float* tWh    = (const float*)d_in[11];
    const float* tbh    = (const float*)d_in[12];
    const float* talpha = (const float*)d_in[13];
    const float* tWf    = (const float*)d_in[14];
    const float* tbf    = (const float*)d_in[15];
    float* out = (float*)d_out;

    cudaFuncSetAttribute(trunk_kernel,
                         cudaFuncAttributeMaxDynamicSharedMemorySize, SMEM_TOTAL);

    prep_weights<<<40, 256>>>(tWh, tWf, talpha);
    branch_kernel<<<NB, HD>>>(params, bW0, bb0, bWh, bbh, balpha, bWf, bbf,
                              tb0, tbh, tbf);

    dim3 grid(NTILES, NB);
    trunk_kernel<<<grid, 256, SMEM_TOTAL>>>(coords, tW0, out);
}

// round 7
// speedup vs baseline: 10.3818x; 1.1334x over previous
#include <cuda_runtime.h>
#include <cuda_fp16.h>
#include <stdint.h>
#include <math.h>

#define NB     16
#define NPTS   50000
#define HD     128
#define NL     5
#define NO     5
#define PDIM   8
#define TILE_M 128
#define NTILES ((NPTS + TILE_M - 1) / TILE_M)
#define LDW    136   // fp16 elems per padded weight row (272B) -> conflict-free ldmatrix

// global scratch (allocation-free per harness rules)
__device__ float g_S [NB * NL * HD];                   // FiLM cumsums [b][l][h]
__device__ float g_bS[NB * NL * HD];                   // bias*S       [b][l][h]
__device__ float g_ZL[NB * NO * HD];                   // branch out   [b][o][h]
__device__ float g_zb[NB * NO];                        // sum_h ZL*bf  [b][o]
__device__ __align__(16) __half g_Wb[5 * HD * LDW];    // [layer][n][LDW] fp16, alpha-folded

// smem layout (bytes)
#define WBUF_BYTES (HD * LDW * 2)                  // 34816
#define OFF_WBUF 0                                 // 2 buffers
#define OFF_W0   (2 * WBUF_BYTES)                  // 69632 : 3*128 f32
#define OFF_S    (OFF_W0 + 3 * HD * 4)             // 5*128 f32
#define OFF_BS   (OFF_S + 5 * HD * 4)              // 5*128 f32
#define OFF_Z    (OFF_BS + 5 * HD * 4)             // 5*128 f32
#define OFF_ZB   (OFF_Z + 5 * HD * 4)              // 8 f32 (5 used)
#define OFF_C    (OFF_ZB + 8 * 4)                  // 128*3 f32
#define SMEM_TOTAL (OFF_C + TILE_M * 3 * 4)        // 83456

// ---------------- helpers ----------------
__device__ __forceinline__ float tanh_fast(float x) {
    float t; asm("tanh.approx.f32 %0, %1;" : "=f"(t) : "f"(x)); return t;
}
__device__ __forceinline__ uint32_t pack_h2(float v0, float v1) {
    __half2 h = __floats2half2_rn(v0, v1);
    return *(uint32_t*)&h;
}
__device__ __forceinline__ uint32_t s2u(const void* p) {
    uint32_t a;
    asm("{ .reg .u64 t; cvta.to.shared.u64 t, %1; cvt.u32.u64 %0, t; }" : "=r"(a) : "l"(p));
    return a;
}
__device__ __forceinline__ void ldmatrix4(uint32_t& r0, uint32_t& r1, uint32_t& r2,
                                          uint32_t& r3, uint32_t addr) {
    asm volatile("ldmatrix.sync.aligned.m8n8.x4.shared.b16 {%0,%1,%2,%3}, [%4];"
                 : "=r"(r0), "=r"(r1), "=r"(r2), "=r"(r3) : "r"(addr));
}
__device__ __forceinline__ void mma_f16(float& d0, float& d1, float& d2, float& d3,
                                        uint32_t a0, uint32_t a1, uint32_t a2, uint32_t a3,
                                        uint32_t b0, uint32_t b1) {
    asm volatile("mma.sync.aligned.m16n8k16.row.col.f32.f16.f16.f32 "
                 "{%0,%1,%2,%3}, {%4,%5,%6,%7}, {%8,%9}, {%0,%1,%2,%3};"
                 : "+f"(d0), "+f"(d1), "+f"(d2), "+f"(d3)
                 : "r"(a0), "r"(a1), "r"(a2), "r"(a3), "r"(b0), "r"(b1));
}
__device__ __forceinline__ void cp_async16(uint32_t saddr, const void* gptr) {
    asm volatile("cp.async.cg.shared.global [%0], [%1], 16;" :: "r"(saddr), "l"(gptr));
}
__device__ __forceinline__ void cp_commit() { asm volatile("cp.async.commit_group;" ::: "memory"); }
__device__ __forceinline__ void cp_wait0()  { asm volatile("cp.async.wait_group 0;"  ::: "memory"); }

// ---------------------------------------------------------------------------
// Prep: transpose trunk weights, fold alpha into input rows -> fp16 planes
// ---------------------------------------------------------------------------
__global__ void prep_weights(const float* __restrict__ Wh, const float* __restrict__ Wf,
                             const float* __restrict__ alpha)
{
    const int t     = blockIdx.x >> 3;              // 0..3: Wh[t], 4: Wf
    const int slice = blockIdx.x & 7;               // 16 n-rows per slice
    const float* W = (t < 4) ? (Wh + t * HD * HD) : Wf;
    const float* al = alpha + t * HD;
    __half* dst = g_Wb + (size_t)t * HD * LDW;
    for (int idx = threadIdx.x; idx < 16 * HD; idx += blockDim.x) {
        int n = slice * 16 + (idx & 15);
        int k = idx >> 4;
        dst[n * LDW + k] = __float2half_rn(W[k * HD + n] * al[k]);
    }
}

// ---------------------------------------------------------------------------
// Branch MLP (exact tanhf): writes g_S, g_bS, g_ZL, g_zb
// ---------------------------------------------------------------------------
__global__ void branch_kernel(const float* __restrict__ params,
                              const float* __restrict__ W0,
                              const float* __restrict__ b0,
                              const float* __restrict__ Wh,
                              const float* __restrict__ bh,
                              const float* __restrict__ alpha,
                              const float* __restrict__ Wf,
                              const float* __restrict__ bf,
                              const float* __restrict__ tb0,
                              const float* __restrict__ tbh,
                              const float* __restrict__ tbf)
{
    const int b = blockIdx.x;
    const int j = threadIdx.x;
    __shared__ float hs[HD];
    __shared__ float ps[PDIM];
    if (j < PDIM) ps[j] = params[b * PDIM + j];
    __syncthreads();

    float acc = b0[j];
#pragma unroll
    for (int k = 0; k < PDIM; ++k) acc = fmaf(ps[k], W0[k * HD + j], acc);
    float hv = alpha[j] * tanhf(acc);
    float S = hv;
    g_S [(b * NL + 0) * HD + j] = S;
    g_bS[(b * NL + 0) * HD + j] = tb0[j] * S;

    for (int i = 0; i < NL - 1; ++i) {
        hs[j] = hv;
        __syncthreads();
        float a2 = bh[i * HD + j];
#pragma unroll 8
        for (int k = 0; k < HD; ++k)
            a2 = fmaf(hs[k], Wh[(i * HD + k) * HD + j], a2);
        hv = alpha[(i + 1) * HD + j] * tanhf(a2);
        S += hv;
        g_S [(b * NL + i + 1) * HD + j] = S;
        g_bS[(b * NL + i + 1) * HD + j] = tbh[i * HD + j] * S;
        __syncthreads();
    }

    hs[j] = hv;
    __syncthreads();

    float zl[NO];
#pragma unroll
    for (int o = 0; o < NO; ++o) {
        float a2 = bf[o * HD + j];
#pragma unroll 8
        for (int k = 0; k < HD; ++k)
            a2 = fmaf(hs[k], Wf[k * (HD * NO) + o * HD + j], a2);
        zl[o] = a2;
        g_ZL[(b * NO + o) * HD + j] = a2;
    }
    float tb = tbf[j];
    __syncthreads();
#pragma unroll
    for (int o = 0; o < NO; ++o) {
        hs[j] = zl[o] * tb;
        __syncthreads();
#pragma unroll
        for (int s = 64; s > 0; s >>= 1) {
            if (j < s) hs[j] += hs[j + s];
            __syncthreads();
        }
        if (j == 0) g_zb[b * NO + o] = hs[0];
        __syncthreads();
    }
}

// ---------------------------------------------------------------------------
// One pp-block (32 output cols = nt 4pp..4pp+3) of a 128x128 layer GEMM.
// Only 16 accumulator regs live at a time.
// ---------------------------------------------------------------------------
__device__ __forceinline__ void mma_block(float (&d)[4][4],
                                          const uint32_t (&ah)[32],
                                          uint32_t wbase, int pp, int lane)
{
    const int grp  = lane >> 3;
    const int nrow = (lane & 7) + ((grp >> 1) << 3);
    const int kcol = (grp & 1) << 3;
    const uint32_t base0 = wbase + (uint32_t)(((nrow + (2 * pp)     * 16) * LDW + kcol) * 2);
    const uint32_t base1 = wbase + (uint32_t)(((nrow + (2 * pp + 1) * 16) * LDW + kcol) * 2);
#pragma unroll
    for (int j = 0; j < 8; ++j) {
        uint32_t b0, b1, b2, b3, c0, c1, c2, c3;
        ldmatrix4(b0, b1, b2, b3, base0 + j * 32);
        ldmatrix4(c0, c1, c2, c3, base1 + j * 32);
        mma_f16(d[0][0], d[0][1], d[0][2], d[0][3],
                ah[4*j], ah[4*j+1], ah[4*j+2], ah[4*j+3], b0, b1);
        mma_f16(d[1][0], d[1][1], d[1][2], d[1][3],
                ah[4*j], ah[4*j+1], ah[4*j+2], ah[4*j+3], b2, b3);
        mma_f16(d[2][0], d[2][1], d[2][2], d[2][3],
                ah[4*j], ah[4*j+1], ah[4*j+2], ah[4*j+3], c0, c1);
        mma_f16(d[3][0], d[3][1], d[3][2], d[3][3],
                ah[4*j], ah[4*j+1], ah[4*j+2], ah[4*j+3], c2, c3);
    }
}

// ---------------------------------------------------------------------------
// Trunk: warp = 16 points x 128 features, activations in registers (fp16).
// 256 threads per CTA = 128 points; 2 CTAs/SM for epilogue/MMA overlap.
// ---------------------------------------------------------------------------
__global__ void __launch_bounds__(256, 2)
trunk_kernel(const float* __restrict__ coords,
             const float* __restrict__ tW0,
             float* __restrict__ out)
{
    extern __shared__ char sm[];
    const uint32_t sbase = s2u(sm);
    const int b    = blockIdx.y;
    const int n0   = blockIdx.x * TILE_M;
    const int nv   = min(TILE_M, NPTS - n0);
    const int tid  = threadIdx.x;
    const int lane = tid & 31;
    const int warp = tid >> 5;
    const int q    = lane & 3;
    const int g4   = lane >> 2;

    float* sW0 = (float*)(sm + OFF_W0);
    float* sS  = (float*)(sm + OFF_S);
    float* sBS = (float*)(sm + OFF_BS);
    float* sZ  = (float*)(sm + OFF_Z);
    float* sZB = (float*)(sm + OFF_ZB);
    float* sC  = (float*)(sm + OFF_C);

    // ---- prologue ----
    {
        const char* src = (const char*)g_Wb;
        uint32_t dst = sbase + OFF_WBUF;
#pragma unroll
        for (int i = tid; i < WBUF_BYTES / 16; i += 256)
            cp_async16(dst + i * 16, src + i * 16);
        cp_commit();
    }
    for (int i = tid; i < 3 * HD; i += 256) sW0[i] = tW0[i];
    for (int i = tid; i < NL * HD; i += 256) {
        sS[i]  = g_S [b * NL * HD + i];
        sBS[i] = g_bS[b * NL * HD + i];
        sZ[i]  = g_ZL[b * NL * HD + i];
    }
    if (tid < NO) sZB[tid] = g_zb[b * NO + tid];
    for (int i = tid; i < TILE_M * 3; i += 256)
        sC[i] = (i < nv * 3) ? coords[((size_t)b * NPTS + n0) * 3 + i] : 0.f;
    cp_wait0();
    __syncthreads();

    uint32_t ah[32];
    const int mlo = warp * 16 + g4;
    const int mhi = mlo + 8;

    // ---- entry layer: v = c@W0 ; x = tanh(v*S0 + b0*S0) (alpha0 folded) ----
    {
        float cl0 = sC[mlo * 3], cl1 = sC[mlo * 3 + 1], cl2 = sC[mlo * 3 + 2];
        float ch0 = sC[mhi * 3], ch1 = sC[mhi * 3 + 1], ch2 = sC[mhi * 3 + 2];
#pragma unroll
        for (int nt = 0; nt < 16; ++nt) {
            int c = nt * 8 + q * 2;
            float2 w0 = *(const float2*)&sW0[c];
            float2 w1 = *(const float2*)&sW0[HD + c];
            float2 w2 = *(const float2*)&sW0[2 * HD + c];
            float2 ss = *(const float2*)&sS[c];
            float2 bs = *(const float2*)&sBS[c];
            float v00 = cl0 * w0.x + cl1 * w1.x + cl2 * w2.x;
            float v01 = cl0 * w0.y + cl1 * w1.y + cl2 * w2.y;
            float v10 = ch0 * w0.x + ch1 * w1.x + ch2 * w2.x;
            float v11 = ch0 * w0.y + ch1 * w1.y + ch2 * w2.y;
            v00 = tanh_fast(fmaf(v00, ss.x, bs.x));
            v01 = tanh_fast(fmaf(v01, ss.y, bs.y));
            v10 = tanh_fast(fmaf(v10, ss.x, bs.x));
            v11 = tanh_fast(fmaf(v11, ss.y, bs.y));
            int base = 4 * (nt >> 1) + (nt & 1) * 2;
            ah[base + 0] = pack_h2(v00, v01);
            ah[base + 1] = pack_h2(v10, v11);
        }
    }

    // ---- hidden layers 0..3 (Wh', alpha-folded) ----
#pragma unroll 1
    for (int g = 0; g < 4; ++g) {
        // prefetch next layer weights into the other buffer
        {
            const char* src = (const char*)g_Wb + (size_t)(g + 1) * WBUF_BYTES;
            uint32_t dst = sbase + OFF_WBUF + (uint32_t)(((g + 1) & 1) * WBUF_BYTES);
#pragma unroll
            for (int i = tid; i < WBUF_BYTES / 16; i += 256)
                cp_async16(dst + i * 16, src + i * 16);
            cp_commit();
        }

        const uint32_t wb = sbase + OFF_WBUF + (uint32_t)((g & 1) * WBUF_BYTES);
        const float* Sv = sS  + (g + 1) * HD;
        const float* Bv = sBS + (g + 1) * HD;
        uint32_t ahn[32];

#pragma unroll
        for (int pp = 0; pp < 4; ++pp) {
            float d[4][4];
#pragma unroll
            for (int t = 0; t < 4; ++t)
#pragma unroll
                for (int r = 0; r < 4; ++r) d[t][r] = 0.f;

            mma_block(d, ah, wb, pp, lane);

            // fused FiLM-tanh epilogue for nt = 4pp..4pp+3 -> ahn[8pp..8pp+7]
#pragma unroll
            for (int t = 0; t < 4; ++t) {
                int nt = 4 * pp + t;
                int c = nt * 8 + q * 2;
                float2 ss = *(const float2*)&Sv[c];
                float2 bs = *(const float2*)&Bv[c];
                float v00 = tanh_fast(fmaf(d[t][0], ss.x, bs.x));
                float v01 = tanh_fast(fmaf(d[t][1], ss.y, bs.y));
                float v10 = tanh_fast(fmaf(d[t][2], ss.x, bs.x));
                float v11 = tanh_fast(fmaf(d[t][3], ss.y, bs.y));
                int base = 8 * pp + 4 * (t >> 1) + 2 * (t & 1);
                ahn[base + 0] = pack_h2(v00, v01);
                ahn[base + 1] = pack_h2(v10, v11);
            }
        }

#pragma unroll
        for (int i = 0; i < 32; ++i) ah[i] = ahn[i];

        cp_wait0();
        __syncthreads();    // buf[(g+1)&1] ready; all reads of buf[g&1] done
    }

    // ---- final layer (Wf', alpha4-folded) + einsum (bf folded into zb) ----
    {
        float po[2][NO];
#pragma unroll
        for (int h = 0; h < 2; ++h)
#pragma unroll
            for (int o = 0; o < NO; ++o) po[h][o] = 0.f;

#pragma unroll
        for (int pp = 0; pp < 4; ++pp) {
            float d[4][4];
#pragma unroll
            for (int t = 0; t < 4; ++t)
#pragma unroll
                for (int r = 0; r < 4; ++r) d[t][r] = 0.f;

            mma_block(d, ah, sbase + OFF_WBUF, pp, lane);   // layer 4 in buf0

#pragma unroll
            for (int t = 0; t < 4; ++t) {
                int nt = 4 * pp + t;
                int c = nt * 8 + q * 2;
#pragma unroll
                for (int o = 0; o < NO; ++o) {
                    float2 z = *(const float2*)&sZ[o * HD + c];
                    po[0][o] = fmaf(d[t][0], z.x, fmaf(d[t][1], z.y, po[0][o]));
                    po[1][o] = fmaf(d[t][2], z.x, fmaf(d[t][3], z.y, po[1][o]));
                }
            }
        }

        // reduce across the 4 lanes of each quad
#pragma unroll
        for (int h = 0; h < 2; ++h)
#pragma unroll
            for (int o = 0; o < NO; ++o) {
                po[h][o] += __shfl_xor_sync(0xffffffffu, po[h][o], 1);
                po[h][o] += __shfl_xor_sync(0xffffffffu, po[h][o], 2);
            }
        if (q == 0) {
            if (mlo < nv) {
                float* op = out + ((size_t)b * NPTS + n0 + mlo) * NO;
#pragma unroll
                for (int o = 0; o < NO; ++o) op[o] = po[0][o] + sZB[o];
            }
            if (mhi < nv) {
                float* op = out + ((size_t)b * NPTS + n0 + mhi) * NO;
#pragma unroll
                for (int o = 0; o < NO; ++o) op[o] = po[1][o] + sZB[o];
            }
        }
    }
}

// ---------------------------------------------------------------------------
// Launch
// ---------------------------------------------------------------------------
extern "C" void kernel_launch(void* const* d_in, const int* in_sizes, int n_in,
                              void* d_out, int out_size)
{
    const float* coords = (const float*)d_in[0];
    const float* params = (const float*)d_in[1];
    const float* bW0    = (const float*)d_in[2];
    const float* bb0    = (const float*)d_in[3];
    const float* bWh    = (const float*)d_in[4];
    const float* bbh    = (const float*)d_in[5];
    const float* balpha = (const float*)d_in[6];
    const float* bWf    = (const float*)d_in[7];
    const float* bbf    = (const float*)d_in[8];
    const float* tW0    = (const float*)d_in[9];
    const float* tb0    = (const float*)d_in[10];
    const float* tWh    = (const float*)d_in[11];
    const float* tbh    = (const float*)d_in[12];
    const float* talpha = (const float*)d_in[13];
    const float* tWf    = (const float*)d_in[14];
    const float* tbf    = (const float*)d_in[15];
    float* out = (float*)d_out;

    cudaFuncSetAttribute(trunk_kernel,
                         cudaFuncAttributeMaxDynamicSharedMemorySize, SMEM_TOTAL);

    prep_weights<<<40, 256>>>(tWh, tWf, talpha);
    branch_kernel<<<NB, HD>>>(params, bW0, bb0, bWh, bbh, balpha, bWf, bbf,
                              tb0, tbh, tbf);

    dim3 grid(NTILES, NB);
    trunk_kernel<<<grid, 256, SMEM_TOTAL>>>(coords, tW0, out);
}

// round 8
// speedup vs baseline: 11.1148x; 1.0706x over previous
#include <cuda_runtime.h>
#include <cuda_fp16.h>
#include <stdint.h>
#include <math.h>

#define NB     16
#define NPTS   50000
#define HD     128
#define NL     5
#define NO     5
#define PDIM   8
#define TILE_M 256
#define TPB    196            // tiles per batch = ceil(50000/256)
#define NJOBS  (NB * TPB)     // 3136
#define NCTA   152
#define NTHR   512
#define LDW    136            // fp16 elems per padded weight row (272B)

// global scratch (allocation-free per harness rules)
__device__ float g_S [NB * NL * HD];
__device__ float g_bS[NB * NL * HD];
__device__ float g_ZL[NB * NO * HD];
__device__ float g_zb[NB * NO];
__device__ __align__(16) __half g_Wb[5 * HD * LDW];    // alpha-folded, transposed

// smem layout (bytes)
#define WBUF_BYTES (HD * LDW * 2)          // 34816
#define OFF_WALL 0                         // 5 layers resident = 174080
#define OFF_W0   174080                    // 3*128 f32 = 1536
#define OFF_S    175616                    // 5*128 f32
#define OFF_BS   178176
#define OFF_Z    180736
#define OFF_ZB   183296                    // 8 f32
#define OFF_C    183328                    // 2 x 256*3 f32 = 6144
#define CBUF     3072
#define SMEM_TOTAL 189472

// ---------------- helpers ----------------
__device__ __forceinline__ float tanh_fast(float x) {
    float t; asm("tanh.approx.f32 %0, %1;" : "=f"(t) : "f"(x)); return t;
}
__device__ __forceinline__ uint32_t pack_h2(float v0, float v1) {
    __half2 h = __floats2half2_rn(v0, v1);
    return *(uint32_t*)&h;
}
__device__ __forceinline__ uint32_t s2u(const void* p) {
    uint32_t a;
    asm("{ .reg .u64 t; cvta.to.shared.u64 t, %1; cvt.u32.u64 %0, t; }" : "=r"(a) : "l"(p));
    return a;
}
__device__ __forceinline__ void ldmatrix4(uint32_t& r0, uint32_t& r1, uint32_t& r2,
                                          uint32_t& r3, uint32_t addr) {
    asm volatile("ldmatrix.sync.aligned.m8n8.x4.shared.b16 {%0,%1,%2,%3}, [%4];"
                 : "=r"(r0), "=r"(r1), "=r"(r2), "=r"(r3) : "r"(addr));
}
__device__ __forceinline__ void mma_f16(float& d0, float& d1, float& d2, float& d3,
                                        uint32_t a0, uint32_t a1, uint32_t a2, uint32_t a3,
                                        uint32_t b0, uint32_t b1) {
    asm volatile("mma.sync.aligned.m16n8k16.row.col.f32.f16.f16.f32 "
                 "{%0,%1,%2,%3}, {%4,%5,%6,%7}, {%8,%9}, {%0,%1,%2,%3};"
                 : "+f"(d0), "+f"(d1), "+f"(d2), "+f"(d3)
                 : "r"(a0), "r"(a1), "r"(a2), "r"(a3), "r"(b0), "r"(b1));
}
__device__ __forceinline__ void cp_async16(uint32_t saddr, const void* gptr) {
    asm volatile("cp.async.cg.shared.global [%0], [%1], 16;" :: "r"(saddr), "l"(gptr));
}
__device__ __forceinline__ void cp_commit() { asm volatile("cp.async.commit_group;" ::: "memory"); }
__device__ __forceinline__ void cp_wait0()  { asm volatile("cp.async.wait_group 0;"  ::: "memory"); }

// ---------------------------------------------------------------------------
// Prep: transpose trunk weights, fold alpha into input rows -> fp16 planes
// ---------------------------------------------------------------------------
__global__ void prep_weights(const float* __restrict__ Wh, const float* __restrict__ Wf,
                             const float* __restrict__ alpha)
{
    const int t     = blockIdx.x >> 3;
    const int slice = blockIdx.x & 7;
    const float* W = (t < 4) ? (Wh + t * HD * HD) : Wf;
    const float* al = alpha + t * HD;
    __half* dst = g_Wb + (size_t)t * HD * LDW;
    for (int idx = threadIdx.x; idx < 16 * HD; idx += blockDim.x) {
        int n = slice * 16 + (idx & 15);
        int k = idx >> 4;
        dst[n * LDW + k] = __float2half_rn(W[k * HD + n] * al[k]);
    }
}

// ---------------------------------------------------------------------------
// Branch MLP (exact tanhf): writes g_S, g_bS, g_ZL, g_zb
// ---------------------------------------------------------------------------
__global__ void branch_kernel(const float* __restrict__ params,
                              const float* __restrict__ W0,
                              const float* __restrict__ b0,
                              const float* __restrict__ Wh,
                              const float* __restrict__ bh,
                              const float* __restrict__ alpha,
                              const float* __restrict__ Wf,
                              const float* __restrict__ bf,
                              const float* __restrict__ tb0,
                              const float* __restrict__ tbh,
                              const float* __restrict__ tbf)
{
    const int b = blockIdx.x;
    const int j = threadIdx.x;
    __shared__ float hs[HD];
    __shared__ float ps[PDIM];
    if (j < PDIM) ps[j] = params[b * PDIM + j];
    __syncthreads();

    float acc = b0[j];
#pragma unroll
    for (int k = 0; k < PDIM; ++k) acc = fmaf(ps[k], W0[k * HD + j], acc);
    float hv = alpha[j] * tanhf(acc);
    float S = hv;
    g_S [(b * NL + 0) * HD + j] = S;
    g_bS[(b * NL + 0) * HD + j] = tb0[j] * S;

    for (int i = 0; i < NL - 1; ++i) {
        hs[j] = hv;
        __syncthreads();
        float a2 = bh[i * HD + j];
#pragma unroll 8
        for (int k = 0; k < HD; ++k)
            a2 = fmaf(hs[k], Wh[(i * HD + k) * HD + j], a2);
        hv = alpha[(i + 1) * HD + j] * tanhf(a2);
        S += hv;
        g_S [(b * NL + i + 1) * HD + j] = S;
        g_bS[(b * NL + i + 1) * HD + j] = tbh[i * HD + j] * S;
        __syncthreads();
    }

    hs[j] = hv;
    __syncthreads();

    float zl[NO];
#pragma unroll
    for (int o = 0; o < NO; ++o) {
        float a2 = bf[o * HD + j];
#pragma unroll 8
        for (int k = 0; k < HD; ++k)
            a2 = fmaf(hs[k], Wf[k * (HD * NO) + o * HD + j], a2);
        zl[o] = a2;
        g_ZL[(b * NO + o) * HD + j] = a2;
    }
    float tb = tbf[j];
    __syncthreads();
#pragma unroll
    for (int o = 0; o < NO; ++o) {
        hs[j] = zl[o] * tb;
        __syncthreads();
#pragma unroll
        for (int s = 64; s > 0; s >>= 1) {
            if (j < s) hs[j] += hs[j + s];
            __syncthreads();
        }
        if (j == 0) g_zb[b * NO + o] = hs[0];
        __syncthreads();
    }
}

// ---------------------------------------------------------------------------
// One pp-block (32 output cols) of a 128x128 layer GEMM; 16 acc regs live.
// ---------------------------------------------------------------------------
__device__ __forceinline__ void mma_block(float (&d)[4][4],
                                          const uint32_t (&ah)[32],
                                          uint32_t wbase, int pp, int lane)
{
    const int grp  = lane >> 3;
    const int nrow = (lane & 7) + ((grp >> 1) << 3);
    const int kcol = (grp & 1) << 3;
    const uint32_t base0 = wbase + (uint32_t)(((nrow + (2 * pp)     * 16) * LDW + kcol) * 2);
    const uint32_t base1 = wbase + (uint32_t)(((nrow + (2 * pp + 1) * 16) * LDW + kcol) * 2);
#pragma unroll
    for (int j = 0; j < 8; ++j) {
        uint32_t b0, b1, b2, b3, c0, c1, c2, c3;
        ldmatrix4(b0, b1, b2, b3, base0 + j * 32);
        ldmatrix4(c0, c1, c2, c3, base1 + j * 32);
        mma_f16(d[0][0], d[0][1], d[0][2], d[0][3],
                ah[4*j], ah[4*j+1], ah[4*j+2], ah[4*j+3], b0, b1);
        mma_f16(d[1][0], d[1][1], d[1][2], d[1][3],
                ah[4*j], ah[4*j+1], ah[4*j+2], ah[4*j+3], b2, b3);
        mma_f16(d[2][0], d[2][1], d[2][2], d[2][3],
                ah[4*j], ah[4*j+1], ah[4*j+2], ah[4*j+3], c0, c1);
        mma_f16(d[3][0], d[3][1], d[3][2], d[3][3],
                ah[4*j], ah[4*j+1], ah[4*j+2], ah[4*j+3], c2, c3);
    }
}

// ---------------------------------------------------------------------------
// Trunk: persistent CTAs. 512 threads = 16 warps = 256 points per tile pass.
// All 5 layers' weights resident in smem; one barrier per tile.
// ---------------------------------------------------------------------------
__global__ void __launch_bounds__(NTHR, 1)
trunk_kernel(const float* __restrict__ coords,
             const float* __restrict__ tW0,
             float* __restrict__ out)
{
    extern __shared__ char sm[];
    const uint32_t sbase = s2u(sm);
    const int tid  = threadIdx.x;
    const int lane = tid & 31;
    const int warp = tid >> 5;
    const int q    = lane & 3;
    const int g4   = lane >> 2;
    const int cta  = blockIdx.x;

    const int jstart = (int)(((long)cta * NJOBS) / NCTA);
    const int jend   = (int)(((long)(cta + 1) * NJOBS) / NCTA);

    float* sW0 = (float*)(sm + OFF_W0);
    float* sS  = (float*)(sm + OFF_S);
    float* sBS = (float*)(sm + OFF_BS);
    float* sZ  = (float*)(sm + OFF_Z);
    float* sZB = (float*)(sm + OFF_ZB);

    // ---- prologue: all 5 layers' weights + first tile's coords ----
    {
        const char* src = (const char*)g_Wb;
#pragma unroll 4
        for (int i = tid; i < 5 * WBUF_BYTES / 16; i += NTHR)
            cp_async16(sbase + OFF_WALL + i * 16, src + i * 16);
        int jb = jstart / TPB, jt = jstart - jb * TPB;
        int nn0 = jt * TILE_M;
        int nnv = min(TILE_M, NPTS - nn0);
        const char* csrc = (const char*)(coords + ((size_t)jb * NPTS + nn0) * 3);
        for (int i = tid; i < nnv * 3 / 4; i += NTHR)
            cp_async16(sbase + OFF_C + i * 16, csrc + i * 16);
        cp_commit();
    }
    for (int i = tid; i < 3 * HD; i += NTHR) sW0[i] = tW0[i];
    cp_wait0();

    const int mlo = warp * 16 + g4;
    const int mhi = mlo + 8;
    int cur_b = -1;
    int p = 0;

    for (int job = jstart; job < jend; ++job) {
        const int b    = job / TPB;
        const int tile = job - b * TPB;
        const int n0   = tile * TILE_M;
        const int nv   = min(TILE_M, NPTS - n0);

        // prefetch next tile's coords into the other buffer
        if (job + 1 < jend) {
            int jb = (job + 1) / TPB, jt = (job + 1) - jb * TPB;
            int nn0 = jt * TILE_M;
            int nnv = min(TILE_M, NPTS - nn0);
            const char* csrc = (const char*)(coords + ((size_t)jb * NPTS + nn0) * 3);
            uint32_t dst = sbase + OFF_C + (uint32_t)((p ^ 1) * CBUF);
            for (int i = tid; i < nnv * 3 / 4; i += NTHR)
                cp_async16(dst + i * 16, csrc + i * 16);
            cp_commit();
        }

        // batch change: reload FiLM vectors (rare)
        if (b != cur_b) {
            for (int i = tid; i < NL * HD; i += NTHR) {
                sS[i]  = g_S [b * NL * HD + i];
                sBS[i] = g_bS[b * NL * HD + i];
                sZ[i]  = g_ZL[b * NL * HD + i];
            }
            if (tid < NO) sZB[tid] = g_zb[b * NO + tid];
            cur_b = b;
            __syncthreads();
        }

        const float* sC = (const float*)(sm + OFF_C + p * CBUF);
        uint32_t ah[32];

        // ---- entry layer ----
        {
            float cl0 = sC[mlo * 3], cl1 = sC[mlo * 3 + 1], cl2 = sC[mlo * 3 + 2];
            float ch0 = sC[mhi * 3], ch1 = sC[mhi * 3 + 1], ch2 = sC[mhi * 3 + 2];
#pragma unroll
            for (int nt = 0; nt < 16; ++nt) {
                int c = nt * 8 + q * 2;
                float2 w0 = *(const float2*)&sW0[c];
                float2 w1 = *(const float2*)&sW0[HD + c];
                float2 w2 = *(const float2*)&sW0[2 * HD + c];
                float2 ss = *(const float2*)&sS[c];
                float2 bs = *(const float2*)&sBS[c];
                float v00 = cl0 * w0.x + cl1 * w1.x + cl2 * w2.x;
                float v01 = cl0 * w0.y + cl1 * w1.y + cl2 * w2.y;
                float v10 = ch0 * w0.x + ch1 * w1.x + ch2 * w2.x;
                float v11 = ch0 * w0.y + ch1 * w1.y + ch2 * w2.y;
                v00 = tanh_fast(fmaf(v00, ss.x, bs.x));
                v01 = tanh_fast(fmaf(v01, ss.y, bs.y));
                v10 = tanh_fast(fmaf(v10, ss.x, bs.x));
                v11 = tanh_fast(fmaf(v11, ss.y, bs.y));
                int base = 4 * (nt >> 1) + (nt & 1) * 2;
                ah[base + 0] = pack_h2(v00, v01);
                ah[base + 1] = pack_h2(v10, v11);
            }
        }

        // ---- hidden layers 0..3 (weights resident, no barriers) ----
#pragma unroll 1
        for (int g = 0; g < 4; ++g) {
            const uint32_t wb = sbase + OFF_WALL + (uint32_t)(g * WBUF_BYTES);
            const float* Sv = sS  + (g + 1) * HD;
            const float* Bv = sBS + (g + 1) * HD;
            uint32_t ahn[32];
#pragma unroll
            for (int pp = 0; pp < 4; ++pp) {
                float d[4][4];
#pragma unroll
                for (int t = 0; t < 4; ++t)
#pragma unroll
                    for (int r = 0; r < 4; ++r) d[t][r] = 0.f;

                mma_block(d, ah, wb, pp, lane);

#pragma unroll
                for (int t = 0; t < 4; ++t) {
                    int nt = 4 * pp + t;
                    int c = nt * 8 + q * 2;
                    float2 ss = *(const float2*)&Sv[c];
                    float2 bs = *(const float2*)&Bv[c];
                    float v00 = tanh_fast(fmaf(d[t][0], ss.x, bs.x));
                    float v01 = tanh_fast(fmaf(d[t][1], ss.y, bs.y));
                    float v10 = tanh_fast(fmaf(d[t][2], ss.x, bs.x));
                    float v11 = tanh_fast(fmaf(d[t][3], ss.y, bs.y));
                    int base = 8 * pp + 4 * (t >> 1) + 2 * (t & 1);
                    ahn[base + 0] = pack_h2(v00, v01);
                    ahn[base + 1] = pack_h2(v10, v11);
                }
            }
#pragma unroll
            for (int i = 0; i < 32; ++i) ah[i] = ahn[i];
        }

        // ---- final layer (Wf') + einsum ----
        {
            float po[2][NO];
#pragma unroll
            for (int h = 0; h < 2; ++h)
#pragma unroll
                for (int o = 0; o < NO; ++o) po[h][o] = 0.f;

#pragma unroll
            for (int pp = 0; pp < 4; ++pp) {
                float d[4][4];
#pragma unroll
                for (int t = 0; t < 4; ++t)
#pragma unroll
                    for (int r = 0; r < 4; ++r) d[t][r] = 0.f;

                mma_block(d, ah, sbase + OFF_WALL + 4u * WBUF_BYTES, pp, lane);

#pragma unroll
                for (int t = 0; t < 4; ++t) {
                    int nt = 4 * pp + t;
                    int c = nt * 8 + q * 2;
#pragma unroll
                    for (int o = 0; o < NO; ++o) {
                        float2 z = *(const float2*)&sZ[o * HD + c];
                        po[0][o] = fmaf(d[t][0], z.x, fmaf(d[t][1], z.y, po[0][o]));
                        po[1][o] = fmaf(d[t][2], z.x, fmaf(d[t][3], z.y, po[1][o]));
                    }
                }
            }
#pragma unroll
            for (int h = 0; h < 2; ++h)
#pragma unroll
                for (int o = 0; o < NO; ++o) {
                    po[h][o] += __shfl_xor_sync(0xffffffffu, po[h][o], 1);
                    po[h][o] += __shfl_xor_sync(0xffffffffu, po[h][o], 2);
                }
            if (q == 0) {
                if (mlo < nv) {
                    float* op = out + ((size_t)b * NPTS + n0 + mlo) * NO;
#pragma unroll
                    for (int o = 0; o < NO; ++o) op[o] = po[0][o] + sZB[o];
                }
                if (mhi < nv) {
                    float* op = out + ((size_t)b * NPTS + n0 + mhi) * NO;
#pragma unroll
                    for (int o = 0; o < NO; ++o) op[o] = po[1][o] + sZB[o];
                }
            }
        }

        cp_wait0();
        __syncthreads();   // next tile's coords visible; all reads of buf p done
        p ^= 1;
    }
}

// ---------------------------------------------------------------------------
// Launch
// ---------------------------------------------------------------------------
extern "C" void kernel_launch(void* const* d_in, const int* in_sizes, int n_in,
                              void* d_out, int out_size)
{
    const float* coords = (const float*)d_in[0];
    const float* params = (const float*)d_in[1];
    const float* bW0    = (const float*)d_in[2];
    const float* bb0    = (const float*)d_in[3];
    const float* bWh    = (const float*)d_in[4];
    const float* bbh    = (const float*)d_in[5];
    const float* balpha = (const float*)d_in[6];
    const float* bWf    = (const float*)d_in[7];
    const float* bbf    = (const float*)d_in[8];
    const float* tW0    = (const float*)d_in[9];
    const float* tb0    = (const float*)d_in[10];
    const float* tWh    = (const float*)d_in[11];
    const float* tbh    = (const float*)d_in[12];
    const float* talpha = (const float*)d_in[13];
    const float* tWf    = (const float*)d_in[14];
    const float* tbf    = (const float*)d_in[15];
    float* out = (float*)d_out;

    cudaFuncSetAttribute(trunk_kernel,
                         cudaFuncAttributeMaxDynamicSharedMemorySize, SMEM_TOTAL);

    prep_weights<<<40, 256>>>(tWh, tWf, talpha);
    branch_kernel<<<NB, HD>>>(params, bW0, bb0, bWh, bbh, balpha, bWf, bbf,
                              tb0, tbh, tbf);

    trunk_kernel<<<NCTA, NTHR, SMEM_TOTAL>>>(coords, tW0, out);
}

// round 9
// speedup vs baseline: 12.1946x; 1.0972x over previous
#include <cuda_runtime.h>
#include <cuda_fp16.h>
#include <stdint.h>
#include <math.h>

#define NB     16
#define NPTS   50000
#define HD     128
#define NL     5
#define NO     5
#define PDIM   8
#define TILE_M 256
#define TPB    196            // ceil(50000/256)
#define NJOBS  (NB * TPB)     // 3136
#define NCTA   152
#define NTHR   256            // 8 warps x m32 = 256 points/tile
#define LDW    136

// global scratch
__device__ float g_S [NB * NL * HD];
__device__ float g_bS[NB * NL * HD];
__device__ float g_ZL[NB * NO * HD];
__device__ float g_zb[NB * NO];
__device__ __align__(16) __half g_Wb[5 * HD * LDW];

// smem layout (bytes)
#define WBUF_BYTES (HD * LDW * 2)          // 34816
#define OFF_WALL 0                         // 5 planes = 174080
#define OFF_W0   174080
#define OFF_S    175616
#define OFF_BS   178176
#define OFF_Z    180736
#define OFF_ZB   183296
#define OFF_C    183328                    // 2 x 256*3 f32
#define CBUF     3072
#define SMEM_TOTAL 189472

// ---------------- helpers ----------------
__device__ __forceinline__ float tanh_fast(float x) {
    float t; asm("tanh.approx.f32 %0, %1;" : "=f"(t) : "f"(x)); return t;
}
__device__ __forceinline__ uint32_t pack_h2(float v0, float v1) {
    __half2 h = __floats2half2_rn(v0, v1);
    return *(uint32_t*)&h;
}
__device__ __forceinline__ uint32_t s2u(const void* p) {
    uint32_t a;
    asm("{ .reg .u64 t; cvta.to.shared.u64 t, %1; cvt.u32.u64 %0, t; }" : "=r"(a) : "l"(p));
    return a;
}
__device__ __forceinline__ void ldmatrix4(uint32_t& r0, uint32_t& r1, uint32_t& r2,
                                          uint32_t& r3, uint32_t addr) {
    asm volatile("ldmatrix.sync.aligned.m8n8.x4.shared.b16 {%0,%1,%2,%3}, [%4];"
                 : "=r"(r0), "=r"(r1), "=r"(r2), "=r"(r3) : "r"(addr));
}
__device__ __forceinline__ void mma_f16(float& d0, float& d1, float& d2, float& d3,
                                        uint32_t a0, uint32_t a1, uint32_t a2, uint32_t a3,
                                        uint32_t b0, uint32_t b1) {
    asm volatile("mma.sync.aligned.m16n8k16.row.col.f32.f16.f16.f32 "
                 "{%0,%1,%2,%3}, {%4,%5,%6,%7}, {%8,%9}, {%0,%1,%2,%3};"
                 : "+f"(d0), "+f"(d1), "+f"(d2), "+f"(d3)
                 : "r"(a0), "r"(a1), "r"(a2), "r"(a3), "r"(b0), "r"(b1));
}
__device__ __forceinline__ void cp_async16(uint32_t saddr, const void* gptr) {
    asm volatile("cp.async.cg.shared.global [%0], [%1], 16;" :: "r"(saddr), "l"(gptr));
}
__device__ __forceinline__ void cp_commit() { asm volatile("cp.async.commit_group;" ::: "memory"); }
__device__ __forceinline__ void cp_wait0()  { asm volatile("cp.async.wait_group 0;"  ::: "memory"); }

// ---------------------------------------------------------------------------
// Prep: transpose trunk weights, fold alpha -> fp16 planes
// ---------------------------------------------------------------------------
__global__ void prep_weights(const float* __restrict__ Wh, const float* __restrict__ Wf,
                             const float* __restrict__ alpha)
{
    const int t     = blockIdx.x >> 3;
    const int slice = blockIdx.x & 7;
    const float* W = (t < 4) ? (Wh + t * HD * HD) : Wf;
    const float* al = alpha + t * HD;
    __half* dst = g_Wb + (size_t)t * HD * LDW;
    for (int idx = threadIdx.x; idx < 16 * HD; idx += blockDim.x) {
        int n = slice * 16 + (idx & 15);
        int k = idx >> 4;
        dst[n * LDW + k] = __float2half_rn(W[k * HD + n] * al[k]);
    }
}

// ---------------------------------------------------------------------------
// Branch MLP (exact tanhf): writes g_S, g_bS, g_ZL, g_zb
// ---------------------------------------------------------------------------
__global__ void branch_kernel(const float* __restrict__ params,
                              const float* __restrict__ W0,
                              const float* __restrict__ b0,
                              const float* __restrict__ Wh,
                              const float* __restrict__ bh,
                              const float* __restrict__ alpha,
                              const float* __restrict__ Wf,
                              const float* __restrict__ bf,
                              const float* __restrict__ tb0,
                              const float* __restrict__ tbh,
                              const float* __restrict__ tbf)
{
    const int b = blockIdx.x;
    const int j = threadIdx.x;
    __shared__ float hs[HD];
    __shared__ float ps[PDIM];
    if (j < PDIM) ps[j] = params[b * PDIM + j];
    __syncthreads();

    float acc = b0[j];
#pragma unroll
    for (int k = 0; k < PDIM; ++k) acc = fmaf(ps[k], W0[k * HD + j], acc);
    float hv = alpha[j] * tanhf(acc);
    float S = hv;
    g_S [(b * NL + 0) * HD + j] = S;
    g_bS[(b * NL + 0) * HD + j] = tb0[j] * S;

    for (int i = 0; i < NL - 1; ++i) {
        hs[j] = hv;
        __syncthreads();
        float a2 = bh[i * HD + j];
#pragma unroll 8
        for (int k = 0; k < HD; ++k)
            a2 = fmaf(hs[k], Wh[(i * HD + k) * HD + j], a2);
        hv = alpha[(i + 1) * HD + j] * tanhf(a2);
        S += hv;
        g_S [(b * NL + i + 1) * HD + j] = S;
        g_bS[(b * NL + i + 1) * HD + j] = tbh[i * HD + j] * S;
        __syncthreads();
    }

    hs[j] = hv;
    __syncthreads();

    float zl[NO];
#pragma unroll
    for (int o = 0; o < NO; ++o) {
        float a2 = bf[o * HD + j];
#pragma unroll 8
        for (int k = 0; k < HD; ++k)
            a2 = fmaf(hs[k], Wf[k * (HD * NO) + o * HD + j], a2);
        zl[o] = a2;
        g_ZL[(b * NO + o) * HD + j] = a2;
    }
    float tb = tbf[j];
    __syncthreads();
#pragma unroll
    for (int o = 0; o < NO; ++o) {
        hs[j] = zl[o] * tb;
        __syncthreads();
#pragma unroll
        for (int s = 64; s > 0; s >>= 1) {
            if (j < s) hs[j] += hs[j + s];
            __syncthreads();
        }
        if (j == 0) g_zb[b * NO + o] = hs[0];
        __syncthreads();
    }
}

// ---------------------------------------------------------------------------
// One pp-block (32 output cols) for an m32 warp tile: 2 m16 blocks share B.
// ---------------------------------------------------------------------------
__device__ __forceinline__ void mma_block32(float (&d)[2][4][4],
                                            const uint32_t (&ah)[2][32],
                                            uint32_t wbase, int pp, int lane)
{
    const int grp  = lane >> 3;
    const int nrow = (lane & 7) + ((grp >> 1) << 3);
    const int kcol = (grp & 1) << 3;
    const uint32_t base0 = wbase + (uint32_t)(((nrow + (2 * pp)     * 16) * LDW + kcol) * 2);
    const uint32_t base1 = wbase + (uint32_t)(((nrow + (2 * pp + 1) * 16) * LDW + kcol) * 2);
#pragma unroll
    for (int j = 0; j < 8; ++j) {
        uint32_t b0, b1, b2, b3, c0, c1, c2, c3;
        ldmatrix4(b0, b1, b2, b3, base0 + j * 32);
        ldmatrix4(c0, c1, c2, c3, base1 + j * 32);
#pragma unroll
        for (int m = 0; m < 2; ++m) {
            mma_f16(d[m][0][0], d[m][0][1], d[m][0][2], d[m][0][3],
                    ah[m][4*j], ah[m][4*j+1], ah[m][4*j+2], ah[m][4*j+3], b0, b1);
            mma_f16(d[m][1][0], d[m][1][1], d[m][1][2], d[m][1][3],
                    ah[m][4*j], ah[m][4*j+1], ah[m][4*j+2], ah[m][4*j+3], b2, b3);
            mma_f16(d[m][2][0], d[m][2][1], d[m][2][2], d[m][2][3],
                    ah[m][4*j], ah[m][4*j+1], ah[m][4*j+2], ah[m][4*j+3], c0, c1);
            mma_f16(d[m][3][0], d[m][3][1], d[m][3][2], d[m][3][3],
                    ah[m][4*j], ah[m][4*j+1], ah[m][4*j+2], ah[m][4*j+3], c2, c3);
        }
    }
}

// ---------------------------------------------------------------------------
// Trunk: persistent CTAs. 256 threads = 8 warps x m32 = 256 points/tile.
// ---------------------------------------------------------------------------
__global__ void __launch_bounds__(NTHR, 1)
trunk_kernel(const float* __restrict__ coords,
             const float* __restrict__ tW0,
             float* __restrict__ out)
{
    extern __shared__ char sm[];
    const uint32_t sbase = s2u(sm);
    const int tid  = threadIdx.x;
    const int lane = tid & 31;
    const int warp = tid >> 5;
    const int q    = lane & 3;
    const int g4   = lane >> 2;
    const int cta  = blockIdx.x;

    const int jstart = (int)(((long)cta * NJOBS) / NCTA);
    const int jend   = (int)(((long)(cta + 1) * NJOBS) / NCTA);

    float* sW0 = (float*)(sm + OFF_W0);
    float* sS  = (float*)(sm + OFF_S);
    float* sBS = (float*)(sm + OFF_BS);
    float* sZ  = (float*)(sm + OFF_Z);
    float* sZB = (float*)(sm + OFF_ZB);

    // ---- prologue ----
    {
        const char* src = (const char*)g_Wb;
#pragma unroll 4
        for (int i = tid; i < 5 * WBUF_BYTES / 16; i += NTHR)
            cp_async16(sbase + OFF_WALL + i * 16, src + i * 16);
        int jb = jstart / TPB, jt = jstart - jb * TPB;
        int nn0 = jt * TILE_M;
        int nnv = min(TILE_M, NPTS - nn0);
        const char* csrc = (const char*)(coords + ((size_t)jb * NPTS + nn0) * 3);
        for (int i = tid; i < nnv * 3 / 4; i += NTHR)
            cp_async16(sbase + OFF_C + i * 16, csrc + i * 16);
        cp_commit();
    }
    for (int i = tid; i < 3 * HD; i += NTHR) sW0[i] = tW0[i];
    cp_wait0();

    const int w32 = warp * 32;
    int cur_b = -1;
    int p = 0;

    for (int job = jstart; job < jend; ++job) {
        const int b    = job / TPB;
        const int tile = job - b * TPB;
        const int n0   = tile * TILE_M;
        const int nv   = min(TILE_M, NPTS - n0);

        // prefetch next tile's coords
        if (job + 1 < jend) {
            int jb = (job + 1) / TPB, jt = (job + 1) - jb * TPB;
            int nn0 = jt * TILE_M;
            int nnv = min(TILE_M, NPTS - nn0);
            const char* csrc = (const char*)(coords + ((size_t)jb * NPTS + nn0) * 3);
            uint32_t dst = sbase + OFF_C + (uint32_t)((p ^ 1) * CBUF);
            for (int i = tid; i < nnv * 3 / 4; i += NTHR)
                cp_async16(dst + i * 16, csrc + i * 16);
            cp_commit();
        }

        if (b != cur_b) {
            for (int i = tid; i < NL * HD; i += NTHR) {
                sS[i]  = g_S [b * NL * HD + i];
                sBS[i] = g_bS[b * NL * HD + i];
                sZ[i]  = g_ZL[b * NL * HD + i];
            }
            if (tid < NO) sZB[tid] = g_zb[b * NO + tid];
            cur_b = b;
            __syncthreads();
        }

        const float* sC = (const float*)(sm + OFF_C + p * CBUF);
        uint32_t ah[2][32];

        // ---- entry layer: 4 row-groups per thread ----
        {
            float cc[4][3];
#pragma unroll
            for (int h = 0; h < 4; ++h) {
                int r = w32 + g4 + 8 * h;
                cc[h][0] = sC[r * 3 + 0];
                cc[h][1] = sC[r * 3 + 1];
                cc[h][2] = sC[r * 3 + 2];
            }
#pragma unroll
            for (int nt = 0; nt < 16; ++nt) {
                int c = nt * 8 + q * 2;
                float2 w0 = *(const float2*)&sW0[c];
                float2 w1 = *(const float2*)&sW0[HD + c];
                float2 w2 = *(const float2*)&sW0[2 * HD + c];
                float2 ss = *(const float2*)&sS[c];
                float2 bs = *(const float2*)&sBS[c];
                int base = 4 * (nt >> 1) + (nt & 1) * 2;
#pragma unroll
                for (int h = 0; h < 4; ++h) {
                    float v0 = cc[h][0] * w0.x + cc[h][1] * w1.x + cc[h][2] * w2.x;
                    float v1 = cc[h][0] * w0.y + cc[h][1] * w1.y + cc[h][2] * w2.y;
                    v0 = tanh_fast(fmaf(v0, ss.x, bs.x));
                    v1 = tanh_fast(fmaf(v1, ss.y, bs.y));
                    ah[h >> 1][base + (h & 1)] = pack_h2(v0, v1);
                }
            }
        }

        // ---- hidden layers 0..3 ----
#pragma unroll 1
        for (int g = 0; g < 4; ++g) {
            const uint32_t wb = sbase + OFF_WALL + (uint32_t)(g * WBUF_BYTES);
            const float* Sv = sS  + (g + 1) * HD;
            const float* Bv = sBS + (g + 1) * HD;
            uint32_t ahn[2][32];
#pragma unroll
            for (int pp = 0; pp < 4; ++pp) {
                float d[2][4][4];
#pragma unroll
                for (int m = 0; m < 2; ++m)
#pragma unroll
                    for (int t = 0; t < 4; ++t)
#pragma unroll
                        for (int r = 0; r < 4; ++r) d[m][t][r] = 0.f;

                mma_block32(d, ah, wb, pp, lane);

#pragma unroll
                for (int t = 0; t < 4; ++t) {
                    int nt = 4 * pp + t;
                    int c = nt * 8 + q * 2;
                    float2 ss = *(const float2*)&Sv[c];
                    float2 bs = *(const float2*)&Bv[c];
                    int base = 8 * pp + 4 * (t >> 1) + 2 * (t & 1);
#pragma unroll
                    for (int m = 0; m < 2; ++m) {
                        float v00 = tanh_fast(fmaf(d[m][t][0], ss.x, bs.x));
                        float v01 = tanh_fast(fmaf(d[m][t][1], ss.y, bs.y));
                        float v10 = tanh_fast(fmaf(d[m][t][2], ss.x, bs.x));
                        float v11 = tanh_fast(fmaf(d[m][t][3], ss.y, bs.y));
                        ahn[m][base + 0] = pack_h2(v00, v01);
                        ahn[m][base + 1] = pack_h2(v10, v11);
                    }
                }
            }
#pragma unroll
            for (int m = 0; m < 2; ++m)
#pragma unroll
                for (int i = 0; i < 32; ++i) ah[m][i] = ahn[m][i];
        }

        // ---- final layer (Wf') + einsum ----
        {
            float po[4][NO];
#pragma unroll
            for (int h = 0; h < 4; ++h)
#pragma unroll
                for (int o = 0; o < NO; ++o) po[h][o] = 0.f;

#pragma unroll
            for (int pp = 0; pp < 4; ++pp) {
                float d[2][4][4];
#pragma unroll
                for (int m = 0; m < 2; ++m)
#pragma unroll
                    for (int t = 0; t < 4; ++t)
#pragma unroll
                        for (int r = 0; r < 4; ++r) d[m][t][r] = 0.f;

                mma_block32(d, ah, sbase + OFF_WALL + 4u * WBUF_BYTES, pp, lane);

#pragma unroll
                for (int t = 0; t < 4; ++t) {
                    int nt = 4 * pp + t;
                    int c = nt * 8 + q * 2;
#pragma unroll
                    for (int o = 0; o < NO; ++o) {
                        float2 z = *(const float2*)&sZ[o * HD + c];
#pragma unroll
                        for (int m = 0; m < 2; ++m) {
                            po[2*m+0][o] = fmaf(d[m][t][0], z.x, fmaf(d[m][t][1], z.y, po[2*m+0][o]));
                            po[2*m+1][o] = fmaf(d[m][t][2], z.x, fmaf(d[m][t][3], z.y, po[2*m+1][o]));
                        }
                    }
                }
            }
#pragma unroll
            for (int h = 0; h < 4; ++h)
#pragma unroll
                for (int o = 0; o < NO; ++o) {
                    po[h][o] += __shfl_xor_sync(0xffffffffu, po[h][o], 1);
                    po[h][o] += __shfl_xor_sync(0xffffffffu, po[h][o], 2);
                }
            if (q == 0) {
#pragma unroll
                for (int h = 0; h < 4; ++h) {
                    int r = w32 + g4 + 8 * h;
                    if (r < nv) {
                        float* op = out + ((size_t)b * NPTS + n0 + r) * NO;
#pragma unroll
                        for (int o = 0; o < NO; ++o) op[o] = po[h][o] + sZB[o];
                    }
                }
            }
        }

        cp_wait0();
        __syncthreads();
        p ^= 1;
    }
}

// ---------------------------------------------------------------------------
// Launch
// ---------------------------------------------------------------------------
extern "C" void kernel_launch(void* const* d_in, const int* in_sizes, int n_in,
                              void* d_out, int out_size)
{
    const float* coords = (const float*)d_in[0];
    const float* params = (const float*)d_in[1];
    const float* bW0    = (const float*)d_in[2];
    const float* bb0    = (const float*)d_in[3];
    const float* bWh    = (const float*)d_in[4];
    const float* bbh    = (const float*)d_in[5];
    const float* balpha = (const float*)d_in[6];
    const float* bWf    = (const float*)d_in[7];
    const float* bbf    = (const float*)d_in[8];
    const float* tW0    = (const float*)d_in[9];
    const float* tb0    = (const float*)d_in[10];
    const float* tWh    = (const float*)d_in[11];
    const float* tbh    = (const float*)d_in[12];
    const float* talpha = (const float*)d_in[13];
    const float* tWf    = (const float*)d_in[14];
    const float* tbf    = (const float*)d_in[15];
    float* out = (float*)d_out;

    cudaFuncSetAttribute(trunk_kernel,
                         cudaFuncAttributeMaxDynamicSharedMemorySize, SMEM_TOTAL);

    prep_weights<<<40, 256>>>(tWh, tWf, talpha);
    branch_kernel<<<NB, HD>>>(params, bW0, bb0, bWh, bbh, balpha, bWf, bbf,
                              tb0, tbh, tbf);

    trunk_kernel<<<NCTA, NTHR, SMEM_TOTAL>>>(coords, tW0, out);
}

// round 11
// speedup vs baseline: 12.8391x; 1.0528x over previous
#include <cuda_runtime.h>
#include <cuda_fp16.h>
#include <stdint.h>
#include <math.h>

#define NB     16
#define NPTS   50000
#define HD     128
#define NL     5
#define NO     5
#define PDIM   8
#define TILE_M 256
#define TPB    196            // ceil(50000/256)
#define NJOBS  (NB * TPB)     // 3136
#define NCTA   152
#define NTHR   256            // 8 warps x m32 = 256 points/tile
#define LDW    136

// global scratch
__device__ float g_S [NB * NL * HD];
__device__ float g_bS[NB * NL * HD];
__device__ float g_zb[NB * NO];
__device__ __align__(16) __half g_Wb[4 * HD * LDW];      // hidden planes 0..3, alpha-folded
__device__ __align__(16) __half g_G [NB * 8 * LDW];      // per-batch folded Wf@Z^T (+alpha4), 8 rows

// smem layout (bytes)
#define WBUF_BYTES (HD * LDW * 2)          // 34816
#define OFF_WALL 0                         // 4 planes = 139264
#define OFF_G    139264                    // 8*LDW fp16 = 2176
#define OFF_W0   141440                    // 3*128 f32
#define OFF_S    142976                    // 5*128 f32
#define OFF_BS   145536                    // 5*128 f32
#define OFF_ZB   148096                    // 8 f32
#define OFF_C    148128                    // 2 x 256*3 f32
#define CBUF     3072
#define SMEM_TOTAL 154272

// ---------------- helpers ----------------
__device__ __forceinline__ float tanh_fast(float x) {
    float t; asm("tanh.approx.f32 %0, %1;" : "=f"(t) : "f"(x)); return t;
}
__device__ __forceinline__ uint32_t pack_h2(float v0, float v1) {
    __half2 h = __floats2half2_rn(v0, v1);
    return *(uint32_t*)&h;
}
__device__ __forceinline__ uint32_t s2u(const void* p) {
    uint32_t a;
    asm("{ .reg .u64 t; cvta.to.shared.u64 t, %1; cvt.u32.u64 %0, t; }" : "=r"(a) : "l"(p));
    return a;
}
__device__ __forceinline__ void ldmatrix4(uint32_t& r0, uint32_t& r1, uint32_t& r2,
                                          uint32_t& r3, uint32_t addr) {
    asm volatile("ldmatrix.sync.aligned.m8n8.x4.shared.b16 {%0,%1,%2,%3}, [%4];"
                 : "=r"(r0), "=r"(r1), "=r"(r2), "=r"(r3) : "r"(addr));
}
__device__ __forceinline__ void ldmatrix2(uint32_t& r0, uint32_t& r1, uint32_t addr) {
    asm volatile("ldmatrix.sync.aligned.m8n8.x2.shared.b16 {%0,%1}, [%2];"
                 : "=r"(r0), "=r"(r1) : "r"(addr));
}
__device__ __forceinline__ void mma_f16(float& d0, float& d1, float& d2, float& d3,
                                        uint32_t a0, uint32_t a1, uint32_t a2, uint32_t a3,
                                        uint32_t b0, uint32_t b1) {
    asm volatile("mma.sync.aligned.m16n8k16.row.col.f32.f16.f16.f32 "
                 "{%0,%1,%2,%3}, {%4,%5,%6,%7}, {%8,%9}, {%0,%1,%2,%3};"
                 : "+f"(d0), "+f"(d1), "+f"(d2), "+f"(d3)
                 : "r"(a0), "r"(a1), "r"(a2), "r"(a3), "r"(b0), "r"(b1));
}
__device__ __forceinline__ void cp_async16(uint32_t saddr, const void* gptr) {
    asm volatile("cp.async.cg.shared.global [%0], [%1], 16;" :: "r"(saddr), "l"(gptr));
}
__device__ __forceinline__ void cp_commit() { asm volatile("cp.async.commit_group;" ::: "memory"); }
__device__ __forceinline__ void cp_wait0()  { asm volatile("cp.async.wait_group 0;"  ::: "memory"); }

// ---------------------------------------------------------------------------
// Prep: transpose hidden trunk weights, fold alpha -> fp16 planes (layers 0..3)
// ---------------------------------------------------------------------------
__global__ void prep_weights(const float* __restrict__ Wh,
                             const float* __restrict__ alpha)
{
    const int t     = blockIdx.x >> 3;              // 0..3
    const int slice = blockIdx.x & 7;
    const float* W = Wh + t * HD * HD;
    const float* al = alpha + t * HD;
    __half* dst = g_Wb + (size_t)t * HD * LDW;
    for (int idx = threadIdx.x; idx < 16 * HD; idx += blockDim.x) {
        int n = slice * 16 + (idx & 15);
        int k = idx >> 4;
        dst[n * LDW + k] = __float2half_rn(W[k * HD + n] * al[k]);
    }
}

// ---------------------------------------------------------------------------
// Branch MLP (exact tanhf): writes g_S, g_bS, g_zb, and folded G = a4*(Wf@Z^T)
// ---------------------------------------------------------------------------
__global__ void branch_kernel(const float* __restrict__ params,
                              const float* __restrict__ W0,
                              const float* __restrict__ b0,
                              const float* __restrict__ Wh,
                              const float* __restrict__ bh,
                              const float* __restrict__ alpha,
                              const float* __restrict__ Wf,
                              const float* __restrict__ bf,
                              const float* __restrict__ tb0,
                              const float* __restrict__ tbh,
                              const float* __restrict__ tbf,
                              const float* __restrict__ tWf,
                              const float* __restrict__ talpha)
{
    const int b = blockIdx.x;
    const int j = threadIdx.x;
    __shared__ float hs[HD];
    __shared__ float ps[PDIM];
    __shared__ float zsh[NO][HD];
    if (j < PDIM) ps[j] = params[b * PDIM + j];
    __syncthreads();

    float acc = b0[j];
#pragma unroll
    for (int k = 0; k < PDIM; ++k) acc = fmaf(ps[k], W0[k * HD + j], acc);
    float hv = alpha[j] * tanhf(acc);
    float S = hv;
    g_S [(b * NL + 0) * HD + j] = S;
    g_bS[(b * NL + 0) * HD + j] = tb0[j] * S;

    for (int i = 0; i < NL - 1; ++i) {
        hs[j] = hv;
        __syncthreads();
        float a2 = bh[i * HD + j];
#pragma unroll 8
        for (int k = 0; k < HD; ++k)
            a2 = fmaf(hs[k], Wh[(i * HD + k) * HD + j], a2);
        hv = alpha[(i + 1) * HD + j] * tanhf(a2);
        S += hv;
        g_S [(b * NL + i + 1) * HD + j] = S;
        g_bS[(b * NL + i + 1) * HD + j] = tbh[i * HD + j] * S;
        __syncthreads();
    }

    hs[j] = hv;
    __syncthreads();

    // ZL rows (branch output) distributed: thread j holds Z[o][h=j]
    float zl[NO];
#pragma unroll
    for (int o = 0; o < NO; ++o) {
        float a2 = bf[o * HD + j];
#pragma unroll 8
        for (int k = 0; k < HD; ++k)
            a2 = fmaf(hs[k], Wf[k * (HD * NO) + o * HD + j], a2);
        zl[o] = a2;
        zsh[o][j] = a2;
    }
    float tb = tbf[j];
    __syncthreads();

    // zb[b][o] = sum_h Z[o][h] * tbf[h]
#pragma unroll
    for (int o = 0; o < NO; ++o) {
        hs[j] = zl[o] * tb;
        __syncthreads();
#pragma unroll
        for (int s = 64; s > 0; s >>= 1) {
            if (j < s) hs[j] += hs[j + s];
            __syncthreads();
        }
        if (j == 0) g_zb[b * NO + o] = hs[0];
        __syncthreads();
    }

    // G[b][o][k] = alpha4[k] * sum_h tWf[k][h] * Z[o][h]   (thread j = k)
    {
        const float* wrow = tWf + j * HD;
        float a4 = talpha[4 * HD + j];
        __half* gdst = g_G + (size_t)b * 8 * LDW;
#pragma unroll
        for (int o = 0; o < NO; ++o) {
            float s = 0.f;
#pragma unroll 8
            for (int h = 0; h < HD; ++h) s = fmaf(wrow[h], zsh[o][h], s);
            gdst[o * LDW + j] = __float2half_rn(s * a4);
        }
#pragma unroll
        for (int o = NO; o < 8; ++o) gdst[o * LDW + j] = __ushort_as_half((unsigned short)0);
    }
}

// ---------------------------------------------------------------------------
// One pp-block (32 output cols) for an m32 warp tile: 2 m16 blocks share B.
// ---------------------------------------------------------------------------
__device__ __forceinline__ void mma_block32(float (&d)[2][4][4],
                                            const uint32_t (&ah)[2][32],
                                            uint32_t wbase, int pp, int lane)
{
    const int grp  = lane >> 3;
    const int nrow = (lane & 7) + ((grp >> 1) << 3);
    const int kcol = (grp & 1) << 3;
    const uint32_t base0 = wbase + (uint32_t)(((nrow + (2 * pp)     * 16) * LDW + kcol) * 2);
    const uint32_t base1 = wbase + (uint32_t)(((nrow + (2 * pp + 1) * 16) * LDW + kcol) * 2);
#pragma unroll
    for (int j = 0; j < 8; ++j) {
        uint32_t b0, b1, b2, b3, c0, c1, c2, c3;
        ldmatrix4(b0, b1, b2, b3, base0 + j * 32);
        ldmatrix4(c0, c1, c2, c3, base1 + j * 32);
#pragma unroll
        for (int m = 0; m < 2; ++m) {
            mma_f16(d[m][0][0], d[m][0][1], d[m][0][2], d[m][0][3],
                    ah[m][4*j], ah[m][4*j+1], ah[m][4*j+2], ah[m][4*j+3], b0, b1);
            mma_f16(d[m][1][0], d[m][1][1], d[m][1][2], d[m][1][3],
                    ah[m][4*j], ah[m][4*j+1], ah[m][4*j+2], ah[m][4*j+3], b2, b3);
            mma_f16(d[m][2][0], d[m][2][1], d[m][2][2], d[m][2][3],
                    ah[m][4*j], ah[m][4*j+1], ah[m][4*j+2], ah[m][4*j+3], c0, c1);
            mma_f16(d[m][3][0], d[m][3][1], d[m][3][2], d[m][3][3],
                    ah[m][4*j], ah[m][4*j+1], ah[m][4*j+2], ah[m][4*j+3], c2, c3);
        }
    }
}

// ---------------------------------------------------------------------------
// Trunk: persistent CTAs. 256 threads = 8 warps x m32 = 256 points/tile.
// Final layer fused into G (n=8 GEMM) — 4 full GEMMs + 1 thin GEMM per tile.
// ---------------------------------------------------------------------------
__global__ void __launch_bounds__(NTHR, 1)
trunk_kernel(const float* __restrict__ coords,
             const float* __restrict__ tW0,
             float* __restrict__ out)
{
    extern __shared__ char sm[];
    const uint32_t sbase = s2u(sm);
    const int tid  = threadIdx.x;
    const int lane = tid & 31;
    const int warp = tid >> 5;
    const int q    = lane & 3;
    const int g4   = lane >> 2;
    const int cta  = blockIdx.x;

    const int jstart = (int)(((long)cta * NJOBS) / NCTA);
    const int jend   = (int)(((long)(cta + 1) * NJOBS) / NCTA);

    float* sW0 = (float*)(sm + OFF_W0);
    float* sS  = (float*)(sm + OFF_S);
    float* sBS = (float*)(sm + OFF_BS);
    float* sZB = (float*)(sm + OFF_ZB);

    // ---- prologue: 4 hidden planes + first coords ----
    {
        const char* src = (const char*)g_Wb;
#pragma unroll 4
        for (int i = tid; i < 4 * WBUF_BYTES / 16; i += NTHR)
            cp_async16(sbase + OFF_WALL + i * 16, src + i * 16);
        int jb = jstart / TPB, jt = jstart - jb * TPB;
        int nn0 = jt * TILE_M;
        int nnv = min(TILE_M, NPTS - nn0);
        const char* csrc = (const char*)(coords + ((size_t)jb * NPTS + nn0) * 3);
        for (int i = tid; i < nnv * 3 / 4; i += NTHR)
            cp_async16(sbase + OFF_C + i * 16, csrc + i * 16);
        cp_commit();
    }
    for (int i = tid; i < 3 * HD; i += NTHR) sW0[i] = tW0[i];
    cp_wait0();

    const int w32 = warp * 32;
    int cur_b = -1;
    int p = 0;

    for (int job = jstart; job < jend; ++job) {
        const int b    = job / TPB;
        const int tile = job - b * TPB;
        const int n0   = tile * TILE_M;
        const int nv   = min(TILE_M, NPTS - n0);

        // prefetch next tile's coords
        if (job + 1 < jend) {
            int jb = (job + 1) / TPB, jt = (job + 1) - jb * TPB;
            int nn0 = jt * TILE_M;
            int nnv = min(TILE_M, NPTS - nn0);
            const char* csrc = (const char*)(coords + ((size_t)jb * NPTS + nn0) * 3);
            uint32_t dst = sbase + OFF_C + (uint32_t)((p ^ 1) * CBUF);
            for (int i = tid; i < nnv * 3 / 4; i += NTHR)
                cp_async16(dst + i * 16, csrc + i * 16);
            cp_commit();
        }

        if (b != cur_b) {
            for (int i = tid; i < NL * HD; i += NTHR) {
                sS[i]  = g_S [b * NL * HD + i];
                sBS[i] = g_bS[b * NL * HD + i];
            }
            {   // folded final-layer matrix G (8 x LDW fp16)
                const uint32_t* gsrc = (const uint32_t*)(g_G + (size_t)b * 8 * LDW);
                uint32_t* gdst = (uint32_t*)(sm + OFF_G);
                for (int i = tid; i < 8 * LDW / 2; i += NTHR) gdst[i] = gsrc[i];
            }
            if (tid < NO) sZB[tid] = g_zb[b * NO + tid];
            cur_b = b;
            __syncthreads();
        }

        const float* sC = (const float*)(sm + OFF_C + p * CBUF);
        uint32_t ah[2][32];

        // ---- entry layer: 4 row-groups per thread ----
        {
            float cc[4][3];
#pragma unroll
            for (int h = 0; h < 4; ++h) {
                int r = w32 + g4 + 8 * h;
                cc[h][0] = sC[r * 3 + 0];
                cc[h][1] = sC[r * 3 + 1];
                cc[h][2] = sC[r * 3 + 2];
            }
#pragma unroll
            for (int nt = 0; nt < 16; ++nt) {
                int c = nt * 8 + q * 2;
                float2 w0 = *(const float2*)&sW0[c];
                float2 w1 = *(const float2*)&sW0[HD + c];
                float2 w2 = *(const float2*)&sW0[2 * HD + c];
                float2 ss = *(const float2*)&sS[c];
                float2 bs = *(const float2*)&sBS[c];
                int base = 4 * (nt >> 1) + (nt & 1) * 2;
#pragma unroll
                for (int h = 0; h < 4; ++h) {
                    float v0 = cc[h][0] * w0.x + cc[h][1] * w1.x + cc[h][2] * w2.x;
                    float v1 = cc[h][0] * w0.y + cc[h][1] * w1.y + cc[h][2] * w2.y;
                    v0 = tanh_fast(fmaf(v0, ss.x, bs.x));
                    v1 = tanh_fast(fmaf(v1, ss.y, bs.y));
                    ah[h >> 1][base + (h & 1)] = pack_h2(v0, v1);
                }
            }
        }

        // ---- hidden layers 0..3 ----
#pragma unroll 1
        for (int g = 0; g < 4; ++g) {
            const uint32_t wb = sbase + OFF_WALL + (uint32_t)(g * WBUF_BYTES);
            const float* Sv = sS  + (g + 1) * HD;
            const float* Bv = sBS + (g + 1) * HD;
            uint32_t ahn[2][32];
#pragma unroll
            for (int pp = 0; pp < 4; ++pp) {
                float d[2][4][4];
#pragma unroll
                for (int m = 0; m < 2; ++m)
#pragma unroll
                    for (int t = 0; t < 4; ++t)
#pragma unroll
                        for (int r = 0; r < 4; ++r) d[m][t][r] = 0.f;

                mma_block32(d, ah, wb, pp, lane);

#pragma unroll
                for (int t = 0; t < 4; ++t) {
                    int nt = 4 * pp + t;
                    int c = nt * 8 + q * 2;
                    float2 ss = *(const float2*)&Sv[c];
                    float2 bs = *(const float2*)&Bv[c];
                    int base = 8 * pp + 4 * (t >> 1) + 2 * (t & 1);
#pragma unroll
                    for (int m = 0; m < 2; ++m) {
                        float v00 = tanh_fast(fmaf(d[m][t][0], ss.x, bs.x));
                        float v01 = tanh_fast(fmaf(d[m][t][1], ss.y, bs.y));
                        float v10 = tanh_fast(fmaf(d[m][t][2], ss.x, bs.x));
                        float v11 = tanh_fast(fmaf(d[m][t][3], ss.y, bs.y));
                        ahn[m][base + 0] = pack_h2(v00, v01);
                        ahn[m][base + 1] = pack_h2(v10, v11);
                    }
                }
            }
#pragma unroll
            for (int m = 0; m < 2; ++m)
#pragma unroll
                for (int i = 0; i < 32; ++i) ah[m][i] = ahn[m][i];
        }

        // ---- final: thin n=8 GEMM against G; D holds out columns directly ----
        {
            float d[2][4];
#pragma unroll
            for (int m = 0; m < 2; ++m)
#pragma unroll
                for (int r = 0; r < 4; ++r) d[m][r] = 0.f;

            // ldmatrix.x2 addresses (lanes 0-15 used): row = lane&7, k-half = (lane>>3)&1
            const uint32_t gaddr = sbase + OFF_G +
                (uint32_t)(((lane & 7) * LDW + ((lane >> 3) & 1) * 8) * 2);
#pragma unroll
            for (int j = 0; j < 8; ++j) {
                uint32_t b0, b1;
                ldmatrix2(b0, b1, gaddr + j * 32);
#pragma unroll
                for (int m = 0; m < 2; ++m)
                    mma_f16(d[m][0], d[m][1], d[m][2], d[m][3],
                            ah[m][4*j], ah[m][4*j+1], ah[m][4*j+2], ah[m][4*j+3], b0, b1);
            }

            const int o0 = 2 * q, o1 = 2 * q + 1;
            const float zb0 = (o0 < NO) ? sZB[o0] : 0.f;
            const float zb1 = (o1 < NO) ? sZB[o1] : 0.f;
#pragma unroll
            for (int m = 0; m < 2; ++m)
#pragma unroll
                for (int half = 0; half < 2; ++half) {
                    int r = w32 + 16 * m + 8 * half + g4;
                    if (r < nv) {
                        float* op = out + ((size_t)b * NPTS + n0 + r) * NO;
                        if (o0 < NO) op[o0] = d[m][2 * half + 0] + zb0;
                        if (o1 < NO) op[o1] = d[m][2 * half + 1] + zb1;
                    }
                }
        }

        cp_wait0();
        __syncthreads();
        p ^= 1;
    }
}

// ---------------------------------------------------------------------------
// Launch
// ---------------------------------------------------------------------------
extern "C" void kernel_launch(void* const* d_in, const int* in_sizes, int n_in,
                              void* d_out, int out_size)
{
    const float* coords = (const float*)d_in[0];
    const float* params = (const float*)d_in[1];
    const float* bW0    = (const float*)d_in[2];
    const float* bb0    = (const float*)d_in[3];
    const float* bWh    = (const float*)d_in[4];
    const float* bbh    = (const float*)d_in[5];
    const float* balpha = (const float*)d_in[6];
    const float* bWf    = (const float*)d_in[7];
    const float* bbf    = (const float*)d_in[8];
    const float* tW0    = (const float*)d_in[9];
    const float* tb0    = (const float*)d_in[10];
    const float* tWh    = (const float*)d_in[11];
    const float* tbh    = (const float*)d_in[12];
    const float* talpha = (const float*)d_in[13];
    const float* tWf    = (const float*)d_in[14];
    const float* tbf    = (const float*)d_in[15];
    float* out = (float*)d_out;

    cudaFuncSetAttribute(trunk_kernel,
                         cudaFuncAttributeMaxDynamicSharedMemorySize, SMEM_TOTAL);

    prep_weights<<<32, 256>>>(tWh, talpha);
    branch_kernel<<<NB, HD>>>(params, bW0, bb0, bWh, bbh, balpha, bWf, bbf,
                              tb0, tbh, tbf, tWf, talpha);

    trunk_kernel<<<NCTA, NTHR, SMEM_TOTAL>>>(coords, tW0, out);
}